// round 1
// baseline (speedup 1.0000x reference)
#include <cuda_runtime.h>
#include <math_constants.h>

#define NB   16
#define CI   64
#define CM   32
#define HW   4096
#define NKV  1024
#define SD   1044   // S row stride in floats: %4==0 (float4), %32==20 (bank-spread)

// Scratch (static device globals; no allocation allowed)
__device__ float Qg[(size_t)NB * CM * HW];   // [B][32][4096] channel-major
__device__ float Kg[(size_t)NB * CM * NKV];  // [B][32][1024] channel-major
__device__ float Vg[(size_t)NB * NKV * CM];  // [B][1024][32] kv-major
__device__ float Yg[(size_t)NB * CM * HW];   // [B][32][4096] channel-major

// ---------------------------------------------------------------------------
// Kernel 1: conv1x1 for theta (Q), phi (K, pooled), origin (V, pooled)
// grid (32 row-pairs, B), 128 threads (2 rows x 64 cols of pixels)
// ---------------------------------------------------------------------------
#define SMEM1_FLOATS (CI*128 + 3*2048 + 2*32*129 + 96)

__global__ void __launch_bounds__(128) qkv_kernel(
    const float* __restrict__ x,
    const float* __restrict__ w_or, const float* __restrict__ b_or,
    const float* __restrict__ w_th, const float* __restrict__ b_th,
    const float* __restrict__ w_ph, const float* __restrict__ b_ph)
{
    extern __shared__ float sm[];
    float* xs   = sm;                 // [64][128]
    float* wth  = xs   + CI * 128;    // [32*64]
    float* wph  = wth  + 2048;
    float* wor  = wph  + 2048;
    float* phis = wor  + 2048;        // [32][129]
    float* orgs = phis + 32 * 129;    // [32][129]
    float* bths = orgs + 32 * 129;    // [32]
    float* bphs = bths + 32;
    float* bors = bphs + 32;

    const int t  = threadIdx.x;       // 0..127
    const int hp = blockIdx.x;        // 0..31 (pair of rows)
    const int b  = blockIdx.y;

    for (int i = t; i < 2048; i += 128) {
        wth[i] = w_th[i]; wph[i] = w_ph[i]; wor[i] = w_or[i];
    }
    if (t < 32) { bths[t] = b_th[t]; bphs[t] = b_ph[t]; bors[t] = b_or[t]; }

    // pixels n = hp*128 + t  (covers rows 2hp, 2hp+1)
    const float* xb = x + ((size_t)b * CI) * HW + hp * 128;
    #pragma unroll
    for (int c = 0; c < CI; ++c) xs[c * 128 + t] = xb[(size_t)c * HW + t];
    __syncthreads();

    // ---- theta -> Qg ----
    {
        float acc[CM];
        #pragma unroll
        for (int o = 0; o < CM; ++o) acc[o] = bths[o];
        for (int c = 0; c < CI; ++c) {
            float xv = xs[c * 128 + t];
            #pragma unroll
            for (int o = 0; o < CM; ++o) acc[o] += wth[o * CI + c] * xv;
        }
        float* Qb = Qg + ((size_t)b * CM) * HW + hp * 128 + t;
        #pragma unroll
        for (int o = 0; o < CM; ++o) Qb[(size_t)o * HW] = acc[o];
    }
    // ---- phi -> phis (smem) ----
    {
        float acc[CM];
        #pragma unroll
        for (int o = 0; o < CM; ++o) acc[o] = bphs[o];
        for (int c = 0; c < CI; ++c) {
            float xv = xs[c * 128 + t];
            #pragma unroll
            for (int o = 0; o < CM; ++o) acc[o] += wph[o * CI + c] * xv;
        }
        #pragma unroll
        for (int o = 0; o < CM; ++o) phis[o * 129 + t] = acc[o];
    }
    // ---- origin -> orgs (smem) ----
    {
        float acc[CM];
        #pragma unroll
        for (int o = 0; o < CM; ++o) acc[o] = bors[o];
        for (int c = 0; c < CI; ++c) {
            float xv = xs[c * 128 + t];
            #pragma unroll
            for (int o = 0; o < CM; ++o) acc[o] += wor[o * CI + c] * xv;
        }
        #pragma unroll
        for (int o = 0; o < CM; ++o) orgs[o * 129 + t] = acc[o];
    }
    __syncthreads();

    // ---- 2x2 maxpool -> Kg (channel-major), Vg (kv-major) ----
    for (int idx = t; idx < CM * 32; idx += 128) {
        {   // K: o = idx>>5, kw = idx&31  (coalesced per channel row)
            int o = idx >> 5, kw = idx & 31;
            const float* p = phis + o * 129 + 2 * kw;
            float m = fmaxf(fmaxf(p[0], p[1]), fmaxf(p[64], p[65]));
            Kg[((size_t)b * CM + o) * NKV + hp * 32 + kw] = m;
        }
        {   // V: o = idx&31, kv = idx>>5  (coalesced per kv row)
            int o = idx & 31, kw = idx >> 5;
            const float* p = orgs + o * 129 + 2 * kw;
            float m = fmaxf(fmaxf(p[0], p[1]), fmaxf(p[64], p[65]));
            Vg[((size_t)b * NKV + hp * 32 + kw) * CM + o] = m;
        }
    }
}

// ---------------------------------------------------------------------------
// Kernel 2: attention. grid (128 q-tiles, B), 256 threads.
// Scores for 32 queries x 1024 keys held in SMEM; softmax in place; PV fused.
// ---------------------------------------------------------------------------
#define SMEM2_FLOATS (32*SD + 1024 + 4096 + 4096 + 32*33 + 32)

__global__ void __launch_bounds__(256) attn_kernel()
{
    extern __shared__ float sm[];
    float* S   = sm;                 // [32][SD]
    float* Qs  = S   + 32 * SD;      // [32 c][32 q]
    float* Ks  = Qs  + 1024;         // [32 c][128 k]
    float* Vs  = Ks  + 4096;         // [128 k][32 c]
    float* ys  = Vs  + 4096;         // [32 q][33]
    float* inv = ys  + 32 * 33;      // [32]

    const int t  = threadIdx.x;
    const int qt = blockIdx.x;       // 0..127
    const int b  = blockIdx.y;
    const int q0 = qt * 32;

    // load Q tile (channel-major): Qs[c][q]
    for (int idx = t; idx < 1024; idx += 256) {
        int c = idx >> 5, q = idx & 31;
        Qs[c * 32 + q] = Qg[((size_t)b * CM + c) * HW + q0 + q];
    }

    // ---------------- Phase 1: S = Q^T K ----------------
    const int tq = t >> 5;   // 0..7 -> 4 q rows each
    const int tk = t & 31;   // 0..31 -> 4 k cols each
    for (int kc = 0; kc < 8; ++kc) {
        __syncthreads();
        for (int idx = t; idx < 4096; idx += 256) {
            int c = idx >> 7, kk = idx & 127;
            Ks[c * 128 + kk] = Kg[((size_t)b * CM + c) * NKV + kc * 128 + kk];
        }
        __syncthreads();
        float4 s0 = {0,0,0,0}, s1 = s0, s2 = s0, s3 = s0;
        #pragma unroll
        for (int c = 0; c < CM; ++c) {
            float4 qv = *(const float4*)&Qs[c * 32 + tq * 4];
            float4 kv = *(const float4*)&Ks[c * 128 + tk * 4];
            s0.x += qv.x*kv.x; s0.y += qv.x*kv.y; s0.z += qv.x*kv.z; s0.w += qv.x*kv.w;
            s1.x += qv.y*kv.x; s1.y += qv.y*kv.y; s1.z += qv.y*kv.z; s1.w += qv.y*kv.w;
            s2.x += qv.z*kv.x; s2.y += qv.z*kv.y; s2.z += qv.z*kv.z; s2.w += qv.z*kv.w;
            s3.x += qv.w*kv.x; s3.y += qv.w*kv.y; s3.z += qv.w*kv.z; s3.w += qv.w*kv.w;
        }
        float* Sp = S + (tq * 4) * SD + kc * 128 + tk * 4;
        *(float4*)&Sp[0]      = s0;
        *(float4*)&Sp[SD]     = s1;
        *(float4*)&Sp[2 * SD] = s2;
        *(float4*)&Sp[3 * SD] = s3;
    }
    __syncthreads();

    // ---------------- Phase 2: softmax over each of 32 rows ----------------
    {
        const int w = t >> 5, lane = t & 31;
        #pragma unroll
        for (int rr = 0; rr < 4; ++rr) {
            int r = w * 4 + rr;
            float4 v[8];
            float m = -CUDART_INF_F;
            #pragma unroll
            for (int i = 0; i < 8; ++i) {
                v[i] = *(const float4*)&S[r * SD + i * 128 + lane * 4];
                m = fmaxf(m, fmaxf(fmaxf(v[i].x, v[i].y), fmaxf(v[i].z, v[i].w)));
            }
            #pragma unroll
            for (int o = 16; o > 0; o >>= 1) m = fmaxf(m, __shfl_xor_sync(0xffffffffu, m, o));
            float ssum = 0.f;
            #pragma unroll
            for (int i = 0; i < 8; ++i) {
                v[i].x = __expf(v[i].x - m); v[i].y = __expf(v[i].y - m);
                v[i].z = __expf(v[i].z - m); v[i].w = __expf(v[i].w - m);
                ssum += (v[i].x + v[i].y) + (v[i].z + v[i].w);
                *(float4*)&S[r * SD + i * 128 + lane * 4] = v[i];
            }
            #pragma unroll
            for (int o = 16; o > 0; o >>= 1) ssum += __shfl_xor_sync(0xffffffffu, ssum, o);
            if (lane == 0) inv[r] = 1.0f / ssum;
        }
    }

    // ---------------- Phase 3: Y = P V ----------------
    const int q  = t >> 3;         // 0..31
    const int c0 = (t & 7) * 4;    // 0,4,...,28
    float4 acc = {0, 0, 0, 0};
    for (int kc = 0; kc < 8; ++kc) {
        __syncthreads();
        for (int idx = t; idx < 4096; idx += 256) {
            int kk = idx >> 5, c = idx & 31;
            Vs[kk * 32 + c] = Vg[((size_t)b * NKV + kc * 128 + kk) * CM + c];
        }
        __syncthreads();
        #pragma unroll 8
        for (int kk = 0; kk < 128; kk += 4) {
            float4 s4 = *(const float4*)&S[q * SD + kc * 128 + kk];
            float4 v0 = *(const float4*)&Vs[(kk + 0) * 32 + c0];
            float4 v1 = *(const float4*)&Vs[(kk + 1) * 32 + c0];
            float4 v2 = *(const float4*)&Vs[(kk + 2) * 32 + c0];
            float4 v3 = *(const float4*)&Vs[(kk + 3) * 32 + c0];
            acc.x += s4.x*v0.x; acc.y += s4.x*v0.y; acc.z += s4.x*v0.z; acc.w += s4.x*v0.w;
            acc.x += s4.y*v1.x; acc.y += s4.y*v1.y; acc.z += s4.y*v1.z; acc.w += s4.y*v1.w;
            acc.x += s4.z*v2.x; acc.y += s4.z*v2.y; acc.z += s4.z*v2.z; acc.w += s4.z*v2.w;
            acc.x += s4.w*v3.x; acc.y += s4.w*v3.y; acc.z += s4.w*v3.z; acc.w += s4.w*v3.w;
        }
    }

    // epilogue: normalize, transpose via smem, write Yg channel-major
    __syncthreads();
    {
        float is = inv[q];
        ys[q * 33 + c0 + 0] = acc.x * is;
        ys[q * 33 + c0 + 1] = acc.y * is;
        ys[q * 33 + c0 + 2] = acc.z * is;
        ys[q * 33 + c0 + 3] = acc.w * is;
    }
    __syncthreads();
    for (int idx = t; idx < 1024; idx += 256) {
        int c = idx >> 5, qq = idx & 31;
        Yg[((size_t)b * CM + c) * HW + q0 + qq] = ys[qq * 33 + c];
    }
}

// ---------------------------------------------------------------------------
// Kernel 3: z = conv1x1(y, w_W) + b_W + x.  grid (16 tiles, B), 256 threads.
// ---------------------------------------------------------------------------
__global__ void __launch_bounds__(256) out_kernel(
    const float* __restrict__ x, const float* __restrict__ w_W,
    const float* __restrict__ b_W, float* __restrict__ out)
{
    __shared__ float ysm[CM * 256];   // [32 c][256 px]
    __shared__ float ws[CI * CM];     // [64][32]
    __shared__ float bs[CI];

    const int t    = threadIdx.x;
    const int tile = blockIdx.x;      // 0..15
    const int b    = blockIdx.y;

    for (int i = t; i < CI * CM; i += 256) ws[i] = w_W[i];
    if (t < CI) bs[t] = b_W[t];
    #pragma unroll
    for (int c = 0; c < CM; ++c)
        ysm[c * 256 + t] = Yg[((size_t)b * CM + c) * HW + tile * 256 + t];
    __syncthreads();

    #pragma unroll
    for (int half = 0; half < 2; ++half) {
        float acc[32];
        #pragma unroll
        for (int o = 0; o < 32; ++o) acc[o] = bs[half * 32 + o];
        for (int c = 0; c < CM; ++c) {
            float yv = ysm[c * 256 + t];
            #pragma unroll
            for (int o = 0; o < 32; ++o) acc[o] += ws[(half * 32 + o) * CM + c] * yv;
        }
        #pragma unroll
        for (int o = 0; o < 32; ++o) {
            int co = half * 32 + o;
            size_t gi = ((size_t)b * CI + co) * HW + tile * 256 + t;
            out[gi] = acc[o] + x[gi];
        }
    }
}

// ---------------------------------------------------------------------------
extern "C" void kernel_launch(void* const* d_in, const int* in_sizes, int n_in,
                              void* d_out, int out_size)
{
    const float* x    = (const float*)d_in[0];
    const float* w_or = (const float*)d_in[1];
    const float* b_or = (const float*)d_in[2];
    const float* w_th = (const float*)d_in[3];
    const float* b_th = (const float*)d_in[4];
    const float* w_ph = (const float*)d_in[5];
    const float* b_ph = (const float*)d_in[6];
    const float* w_W  = (const float*)d_in[7];
    const float* b_W  = (const float*)d_in[8];
    float* out = (float*)d_out;

    const int smem1 = SMEM1_FLOATS * 4;   // ~90.8 KB
    const int smem2 = SMEM2_FLOATS * 4;   // ~174.9 KB
    cudaFuncSetAttribute(qkv_kernel,  cudaFuncAttributeMaxDynamicSharedMemorySize, smem1);
    cudaFuncSetAttribute(attn_kernel, cudaFuncAttributeMaxDynamicSharedMemorySize, smem2);

    qkv_kernel<<<dim3(32, NB), 128, smem1>>>(x, w_or, b_or, w_th, b_th, w_ph, b_ph);
    attn_kernel<<<dim3(128, NB), 256, smem2>>>();
    out_kernel<<<dim3(16, NB), 256>>>(x, w_W, b_W, out);
}

// round 3
// speedup vs baseline: 5.8267x; 5.8267x over previous
#include <cuda_runtime.h>
#include <cuda_fp16.h>

#define NB   16
#define CI   64
#define CM   32
#define HW   4096
#define NKV  1024

// Scratch (static device globals; no allocation allowed)
__device__ __half Qh[(size_t)NB * HW * CM];    // [B][4096 q][32 c]
__device__ __half Kh[(size_t)NB * NKV * CM];   // [B][1024 kv][32 c]
__device__ __half Vth[(size_t)NB * CM * NKV];  // [B][32 c][1024 kv]
__device__ float  Yg[(size_t)NB * HW * CM];    // [B][4096 q][32 c]

// ---------------------------------------------------------------------------
// helpers
// ---------------------------------------------------------------------------
__device__ __forceinline__ unsigned smem_u32(const void* p) {
    return (unsigned)__cvta_generic_to_shared(p);
}

__device__ __forceinline__ void ldmx4(unsigned& r0, unsigned& r1, unsigned& r2,
                                      unsigned& r3, unsigned addr) {
    asm volatile("ldmatrix.sync.aligned.m8n8.x4.shared.b16 {%0,%1,%2,%3}, [%4];\n"
                 : "=r"(r0), "=r"(r1), "=r"(r2), "=r"(r3) : "r"(addr));
}

__device__ __forceinline__ void mma16816(float* dd, const unsigned* aa,
                                         const unsigned* bb, const float* cc) {
    asm volatile(
        "mma.sync.aligned.m16n8k16.row.col.f32.f16.f16.f32 "
        "{%0,%1,%2,%3},{%4,%5,%6,%7},{%8,%9},{%10,%11,%12,%13};\n"
        : "=f"(dd[0]), "=f"(dd[1]), "=f"(dd[2]), "=f"(dd[3])
        : "r"(aa[0]), "r"(aa[1]), "r"(aa[2]), "r"(aa[3]),
          "r"(bb[0]), "r"(bb[1]),
          "f"(cc[0]), "f"(cc[1]), "f"(cc[2]), "f"(cc[3]));
}

__device__ __forceinline__ unsigned packh2(float av, float bv) {
    __half2 hh = __floats2half2_rn(av, bv);
    return *(unsigned*)&hh;
}

// ---------------------------------------------------------------------------
// Kernel 1: conv1x1 theta/phi/origin (+pool) -> Qh, Kh, Vth (half)
// grid (32 row-pairs, B), 128 threads
// ---------------------------------------------------------------------------
#define SMEM1_FLOATS (CI*128 + 3*2048 + 32*129 + 96)

__global__ void __launch_bounds__(128) qkv_kernel(
    const float* __restrict__ xg,
    const float* __restrict__ w_or, const float* __restrict__ b_or,
    const float* __restrict__ w_th, const float* __restrict__ b_th,
    const float* __restrict__ w_ph, const float* __restrict__ b_ph)
{
    extern __shared__ float smf[];
    float* xs   = smf;
    float* wth  = xs  + CI * 128;
    float* wph  = wth + 2048;
    float* wor  = wph + 2048;
    float* stg  = wor + 2048;          // [32][129] staging
    float* bths = stg + 32 * 129;
    float* bphs = bths + 32;
    float* bors = bphs + 32;

    const int t  = threadIdx.x;
    const int hp = blockIdx.x;
    const int b  = blockIdx.y;

    for (int i = t; i < 2048; i += 128) {
        wth[i] = w_th[i];
        wph[i] = w_ph[i];
        wor[i] = w_or[i];
    }
    if (t < 32) {
        bths[t] = b_th[t];
        bphs[t] = b_ph[t];
        bors[t] = b_or[t];
    }

    const float* xb = xg + ((size_t)b * CI) * HW + hp * 128;
    #pragma unroll
    for (int c = 0; c < CI; ++c) {
        xs[c * 128 + t] = xb[(size_t)c * HW + t];
    }
    __syncthreads();

    // ================= theta -> Qh =================
    {
        float acc[CM];
        #pragma unroll
        for (int o = 0; o < CM; ++o) {
            acc[o] = bths[o];
        }
        #pragma unroll 4
        for (int c = 0; c < CI; c += 4) {
            float x0 = xs[(c+0)*128 + t];
            float x1 = xs[(c+1)*128 + t];
            float x2 = xs[(c+2)*128 + t];
            float x3 = xs[(c+3)*128 + t];
            #pragma unroll
            for (int o = 0; o < CM; ++o) {
                float4 w4 = *(const float4*)&wth[o * CI + c];
                acc[o] += w4.x*x0 + w4.y*x1 + w4.z*x2 + w4.w*x3;
            }
        }
        #pragma unroll
        for (int o = 0; o < CM; ++o) {
            stg[o * 129 + t] = acc[o];
        }
    }
    __syncthreads();
    {
        __half2* Qb = (__half2*)(Qh + ((size_t)b * HW + hp * 128) * CM);
        #pragma unroll
        for (int i = 0; i < 16; ++i) {
            int idx = t + i * 128;
            int q = idx >> 4;
            int cp = idx & 15;
            float lo = stg[(2*cp) * 129 + q];
            float hi = stg[(2*cp+1) * 129 + q];
            Qb[q * 16 + cp] = __floats2half2_rn(lo, hi);
        }
    }

    // ================= phi -> pooled Kh =================
    {
        float acc[CM];
        #pragma unroll
        for (int o = 0; o < CM; ++o) {
            acc[o] = bphs[o];
        }
        #pragma unroll 4
        for (int c = 0; c < CI; c += 4) {
            float x0 = xs[(c+0)*128 + t];
            float x1 = xs[(c+1)*128 + t];
            float x2 = xs[(c+2)*128 + t];
            float x3 = xs[(c+3)*128 + t];
            #pragma unroll
            for (int o = 0; o < CM; ++o) {
                float4 w4 = *(const float4*)&wph[o * CI + c];
                acc[o] += w4.x*x0 + w4.y*x1 + w4.z*x2 + w4.w*x3;
            }
        }
        __syncthreads();
        #pragma unroll
        for (int o = 0; o < CM; ++o) {
            stg[o * 129 + t] = acc[o];
        }
    }
    __syncthreads();
    {
        #pragma unroll
        for (int i = 0; i < 8; ++i) {
            int idx = t + i * 128;
            int kw = idx >> 5;
            int o = idx & 31;
            const float* pp = stg + o * 129 + 2 * kw;
            float mv = fmaxf(fmaxf(pp[0], pp[1]), fmaxf(pp[64], pp[65]));
            Kh[((size_t)b * NKV + hp * 32 + kw) * CM + o] = __float2half(mv);
        }
    }

    // ================= origin -> pooled Vth =================
    {
        float acc[CM];
        #pragma unroll
        for (int o = 0; o < CM; ++o) {
            acc[o] = bors[o];
        }
        #pragma unroll 4
        for (int c = 0; c < CI; c += 4) {
            float x0 = xs[(c+0)*128 + t];
            float x1 = xs[(c+1)*128 + t];
            float x2 = xs[(c+2)*128 + t];
            float x3 = xs[(c+3)*128 + t];
            #pragma unroll
            for (int o = 0; o < CM; ++o) {
                float4 w4 = *(const float4*)&wor[o * CI + c];
                acc[o] += w4.x*x0 + w4.y*x1 + w4.z*x2 + w4.w*x3;
            }
        }
        __syncthreads();
        #pragma unroll
        for (int o = 0; o < CM; ++o) {
            stg[o * 129 + t] = acc[o];
        }
    }
    __syncthreads();
    {
        #pragma unroll
        for (int i = 0; i < 8; ++i) {
            int idx = t + i * 128;
            int o = idx >> 5;
            int kw = idx & 31;
            const float* pp = stg + o * 129 + 2 * kw;
            float mv = fmaxf(fmaxf(pp[0], pp[1]), fmaxf(pp[64], pp[65]));
            Vth[((size_t)b * CM + o) * NKV + hp * 32 + kw] = __float2half(mv);
        }
    }
}

// ---------------------------------------------------------------------------
// Kernel 2: attention via mma.sync (fp16 in, fp32 accum), online softmax.
// grid (32 q-tiles of 128, B), 256 threads = 8 warps (16 q rows each).
// ---------------------------------------------------------------------------
#define QSTR 40
#define VSTR 72

__global__ void __launch_bounds__(256) attn_kernel()
{
    __shared__ __half Qsm[128 * QSTR];
    __shared__ __half Ksm[64 * QSTR];
    __shared__ __half Vsm[32 * VSTR];
    __shared__ float  Ysm[128 * 33];

    const int t    = threadIdx.x;
    const int warp = t >> 5;
    const int lane = t & 31;
    const int b    = blockIdx.y;
    const int q0   = blockIdx.x * 128;

    // load Q tile: 128 rows x 32 halfs = 512 uint4
    {
        #pragma unroll
        for (int i = 0; i < 2; ++i) {
            int idx = t + i * 256;
            int row = idx >> 2;
            int seg = idx & 3;
            const uint4* src = (const uint4*)(Qh + ((size_t)b * HW + q0 + row) * CM) + seg;
            *(uint4*)&Qsm[row * QSTR + seg * 8] = *src;
        }
    }
    __syncthreads();

    // A-operand (Q) fragments for 2 k-steps
    unsigned aQ0[4];
    unsigned aQ1[4];
    {
        int arow = lane & 15;
        int acol = (lane >> 4) << 3;
        unsigned base = smem_u32(Qsm);
        unsigned ad0 = base + (((warp * 16 + arow) * QSTR + acol) << 1);
        ldmx4(aQ0[0], aQ0[1], aQ0[2], aQ0[3], ad0);
        ldmx4(aQ1[0], aQ1[1], aQ1[2], aQ1[3], ad0 + 32);
    }

    const int brow = ((lane >> 4) << 3) + (lane & 7);
    const int bcol = ((lane >> 3) & 1) << 3;
    const unsigned ksBase = smem_u32(Ksm);
    const unsigned vsBase = smem_u32(Vsm);

    float oAcc[4][4];
    #pragma unroll
    for (int n = 0; n < 4; ++n) {
        oAcc[n][0] = 0.f; oAcc[n][1] = 0.f; oAcc[n][2] = 0.f; oAcc[n][3] = 0.f;
    }
    float m_lo = -1e30f;
    float m_hi = -1e30f;
    float l_lo = 0.f;
    float l_hi = 0.f;

    for (int kc = 0; kc < 16; ++kc) {
        __syncthreads();
        {
            int row = t >> 2;
            int seg = t & 3;
            const uint4* src = (const uint4*)(Kh + ((size_t)b * NKV + kc * 64 + row) * CM) + seg;
            *(uint4*)&Ksm[row * QSTR + seg * 8] = *src;
        }
        {
            int row = t >> 3;
            int seg = t & 7;
            const uint4* src = (const uint4*)(Vth + ((size_t)b * CM + row) * NKV + kc * 64) + seg;
            *(uint4*)&Vsm[row * VSTR + seg * 8] = *src;
        }
        __syncthreads();

        // sAcc = Q K^T for this 64-kv chunk
        float sAcc[8][4];
        #pragma unroll
        for (int j = 0; j < 8; ++j) {
            sAcc[j][0] = 0.f; sAcc[j][1] = 0.f; sAcc[j][2] = 0.f; sAcc[j][3] = 0.f;
        }
        #pragma unroll
        for (int g = 0; g < 4; ++g) {
            unsigned bkf[4];
            unsigned ra = ksBase + (((g * 16 + brow) * QSTR + bcol) << 1);
            ldmx4(bkf[0], bkf[1], bkf[2], bkf[3], ra);
            mma16816(sAcc[2*g],   aQ0, &bkf[0], sAcc[2*g]);
            mma16816(sAcc[2*g+1], aQ0, &bkf[2], sAcc[2*g+1]);
            ldmx4(bkf[0], bkf[1], bkf[2], bkf[3], ra + 32);
            mma16816(sAcc[2*g],   aQ1, &bkf[0], sAcc[2*g]);
            mma16816(sAcc[2*g+1], aQ1, &bkf[2], sAcc[2*g+1]);
        }

        // online softmax update
        float mlo = -1e30f;
        float mhi = -1e30f;
        #pragma unroll
        for (int j = 0; j < 8; ++j) {
            mlo = fmaxf(mlo, fmaxf(sAcc[j][0], sAcc[j][1]));
            mhi = fmaxf(mhi, fmaxf(sAcc[j][2], sAcc[j][3]));
        }
        mlo = fmaxf(mlo, __shfl_xor_sync(0xffffffffu, mlo, 1));
        mlo = fmaxf(mlo, __shfl_xor_sync(0xffffffffu, mlo, 2));
        mhi = fmaxf(mhi, __shfl_xor_sync(0xffffffffu, mhi, 1));
        mhi = fmaxf(mhi, __shfl_xor_sync(0xffffffffu, mhi, 2));
        float nmlo = fmaxf(m_lo, mlo);
        float nmhi = fmaxf(m_hi, mhi);
        float sclo = __expf(m_lo - nmlo);
        float schi = __expf(m_hi - nmhi);
        m_lo = nmlo;
        m_hi = nmhi;

        float slo = 0.f;
        float shi = 0.f;
        unsigned pPk[8][2];
        #pragma unroll
        for (int j = 0; j < 8; ++j) {
            float p0 = __expf(sAcc[j][0] - nmlo);
            float p1 = __expf(sAcc[j][1] - nmlo);
            float p2 = __expf(sAcc[j][2] - nmhi);
            float p3 = __expf(sAcc[j][3] - nmhi);
            slo += p0 + p1;
            shi += p2 + p3;
            pPk[j][0] = packh2(p0, p1);
            pPk[j][1] = packh2(p2, p3);
        }
        slo += __shfl_xor_sync(0xffffffffu, slo, 1);
        slo += __shfl_xor_sync(0xffffffffu, slo, 2);
        shi += __shfl_xor_sync(0xffffffffu, shi, 1);
        shi += __shfl_xor_sync(0xffffffffu, shi, 2);
        l_lo = l_lo * sclo + slo;
        l_hi = l_hi * schi + shi;
        #pragma unroll
        for (int n = 0; n < 4; ++n) {
            oAcc[n][0] *= sclo;
            oAcc[n][1] *= sclo;
            oAcc[n][2] *= schi;
            oAcc[n][3] *= schi;
        }

        // oAcc += P V
        #pragma unroll
        for (int s = 0; s < 4; ++s) {
            unsigned aP[4];
            aP[0] = pPk[2*s][0];
            aP[1] = pPk[2*s][1];
            aP[2] = pPk[2*s+1][0];
            aP[3] = pPk[2*s+1][1];
            #pragma unroll
            for (int pr = 0; pr < 2; ++pr) {
                unsigned bvf[4];
                unsigned rv = vsBase + (((pr * 16 + brow) * VSTR + s * 16 + bcol) << 1);
                ldmx4(bvf[0], bvf[1], bvf[2], bvf[3], rv);
                mma16816(oAcc[2*pr],   aP, &bvf[0], oAcc[2*pr]);
                mma16816(oAcc[2*pr+1], aP, &bvf[2], oAcc[2*pr+1]);
            }
        }
    }

    // epilogue: normalize, stage, write Yg [q][c]
    {
        float ilo = 1.0f / l_lo;
        float ihi = 1.0f / l_hi;
        int rlo = warp * 16 + (lane >> 2);
        int cb  = (lane & 3) * 2;
        #pragma unroll
        for (int n = 0; n < 4; ++n) {
            int c = n * 8 + cb;
            Ysm[rlo * 33 + c]         = oAcc[n][0] * ilo;
            Ysm[rlo * 33 + c + 1]     = oAcc[n][1] * ilo;
            Ysm[(rlo + 8) * 33 + c]   = oAcc[n][2] * ihi;
            Ysm[(rlo + 8) * 33 + c+1] = oAcc[n][3] * ihi;
        }
    }
    __syncthreads();
    {
        float* Yb = Yg + ((size_t)b * HW + q0) * CM;
        #pragma unroll
        for (int i = 0; i < 16; ++i) {
            int idx = t + i * 256;
            int n = idx >> 5;
            int c = idx & 31;
            Yb[n * CM + c] = Ysm[n * 33 + c];
        }
    }
}

// ---------------------------------------------------------------------------
// Kernel 3: z = conv1x1(y, w_W) + b_W + x.  grid (16 tiles, B), 256 threads.
// ---------------------------------------------------------------------------
__global__ void __launch_bounds__(256) out_kernel(
    const float* __restrict__ xg, const float* __restrict__ w_W,
    const float* __restrict__ b_W, float* __restrict__ outg)
{
    __shared__ float ysm[256 * 33];
    __shared__ float ws[CI * CM];
    __shared__ float bsd[CI];

    const int t    = threadIdx.x;
    const int tile = blockIdx.x;
    const int b    = blockIdx.y;

    for (int i = t; i < CI * CM; i += 256) {
        ws[i] = w_W[i];
    }
    if (t < CI) {
        bsd[t] = b_W[t];
    }
    {
        const float* Yb = Yg + ((size_t)b * HW + tile * 256) * CM;
        #pragma unroll
        for (int i = 0; i < 32; ++i) {
            int idx = t + i * 256;
            int n = idx >> 5;
            int c = idx & 31;
            ysm[n * 33 + c] = Yb[n * CM + c];
        }
    }
    __syncthreads();

    #pragma unroll
    for (int half = 0; half < 2; ++half) {
        float acc[32];
        #pragma unroll
        for (int o = 0; o < 32; ++o) {
            acc[o] = bsd[half * 32 + o];
        }
        #pragma unroll 4
        for (int c = 0; c < CM; c += 4) {
            float y0 = ysm[t * 33 + c];
            float y1 = ysm[t * 33 + c + 1];
            float y2 = ysm[t * 33 + c + 2];
            float y3 = ysm[t * 33 + c + 3];
            #pragma unroll
            for (int o = 0; o < 32; ++o) {
                float4 w4 = *(const float4*)&ws[(half * 32 + o) * CM + c];
                acc[o] += w4.x*y0 + w4.y*y1 + w4.z*y2 + w4.w*y3;
            }
        }
        #pragma unroll
        for (int o = 0; o < 32; ++o) {
            int co = half * 32 + o;
            size_t gi = ((size_t)b * CI + co) * HW + tile * 256 + t;
            outg[gi] = acc[o] + xg[gi];
        }
    }
}

// ---------------------------------------------------------------------------
extern "C" void kernel_launch(void* const* d_in, const int* in_sizes, int n_in,
                              void* d_out, int out_size)
{
    const float* xg   = (const float*)d_in[0];
    const float* w_or = (const float*)d_in[1];
    const float* b_or = (const float*)d_in[2];
    const float* w_th = (const float*)d_in[3];
    const float* b_th = (const float*)d_in[4];
    const float* w_ph = (const float*)d_in[5];
    const float* b_ph = (const float*)d_in[6];
    const float* w_W  = (const float*)d_in[7];
    const float* b_W  = (const float*)d_in[8];
    float* outg = (float*)d_out;

    const int smem1 = SMEM1_FLOATS * 4;
    cudaFuncSetAttribute(qkv_kernel, cudaFuncAttributeMaxDynamicSharedMemorySize, smem1);

    qkv_kernel<<<dim3(32, NB), 128, smem1>>>(xg, w_or, b_or, w_th, b_th, w_ph, b_ph);
    attn_kernel<<<dim3(32, NB), 256>>>();
    out_kernel<<<dim3(16, NB), 256>>>(xg, w_W, b_W, outg);
}

// round 5
// speedup vs baseline: 8.7969x; 1.5098x over previous
#include <cuda_runtime.h>
#include <cuda_fp16.h>

#define NB   16
#define CI   64
#define CM   32
#define HW   4096
#define NKV  1024

// Scratch (static device globals; no allocation allowed)
__device__ __half Qh[(size_t)NB * HW * CM];    // [B][4096 q][32 c]
__device__ __half Kh[(size_t)NB * NKV * CM];   // [B][1024 kv][32 c]
__device__ __half Vth[(size_t)NB * CM * NKV];  // [B][32 c][1024 kv]
__device__ __half Yh[(size_t)NB * HW * CM];    // [B][4096 q][32 c]

// ---------------------------------------------------------------------------
// helpers
// ---------------------------------------------------------------------------
__device__ __forceinline__ unsigned smem_u32(const void* p) {
    return (unsigned)__cvta_generic_to_shared(p);
}

__device__ __forceinline__ void ldmx4(unsigned& r0, unsigned& r1, unsigned& r2,
                                      unsigned& r3, unsigned addr) {
    asm volatile("ldmatrix.sync.aligned.m8n8.x4.shared.b16 {%0,%1,%2,%3}, [%4];\n"
                 : "=r"(r0), "=r"(r1), "=r"(r2), "=r"(r3) : "r"(addr));
}

__device__ __forceinline__ void mma16816(float* dd, const unsigned* aa,
                                         const unsigned* bb, const float* cc) {
    asm volatile(
        "mma.sync.aligned.m16n8k16.row.col.f32.f16.f16.f32 "
        "{%0,%1,%2,%3},{%4,%5,%6,%7},{%8,%9},{%10,%11,%12,%13};\n"
        : "=f"(dd[0]), "=f"(dd[1]), "=f"(dd[2]), "=f"(dd[3])
        : "r"(aa[0]), "r"(aa[1]), "r"(aa[2]), "r"(aa[3]),
          "r"(bb[0]), "r"(bb[1]),
          "f"(cc[0]), "f"(cc[1]), "f"(cc[2]), "f"(cc[3]));
}

__device__ __forceinline__ unsigned packh2(float av, float bv) {
    __half2 hh = __floats2half2_rn(av, bv);
    return *(unsigned*)&hh;
}

#define CP_ASYNC16(sa, g) \
    asm volatile("cp.async.cg.shared.global [%0], [%1], 16;\n" :: "r"(sa), "l"(g))
#define CP_COMMIT() asm volatile("cp.async.commit_group;\n")
#define CP_WAIT0()  asm volatile("cp.async.wait_group 0;\n" ::: "memory")

// ---------------------------------------------------------------------------
// Kernel 1: qkv via tensor cores.
// Per block: GEMM [128 px] x [96 outs] over K=64 channels, fp16 in / fp32 acc.
// grid (32 row-pairs, B), 128 threads = 4 warps (32 px strip each).
// ---------------------------------------------------------------------------
#define XSTR 72    // xsh row stride in halfs (144B = 9x16B, ldmatrix-friendly)
#define WSTR 72
#define SMEM1_BYTES (32768 + 18432 + 13824 + 384)

__global__ void __launch_bounds__(128) qkv_kernel(
    const float* __restrict__ xg,
    const float* __restrict__ w_or, const float* __restrict__ b_or,
    const float* __restrict__ w_th, const float* __restrict__ b_th,
    const float* __restrict__ w_ph, const float* __restrict__ b_ph)
{
    extern __shared__ char smraw[];
    float*  xs32 = (float*)smraw;                            // [64 c][128 px]
    __half* xsh  = (__half*)(smraw + 32768);                 // [128 px][XSTR]
    __half* wsh  = (__half*)(smraw + 32768 + 18432);         // [96 out][WSTR]
    float*  bias = (float*)(smraw + 32768 + 18432 + 13824);  // [96]
    float*  stg  = xs32;                                     // alias: [128 px][33]

    const int t    = threadIdx.x;
    const int warp = t >> 5;
    const int lane = t & 31;
    const int hp   = blockIdx.x;
    const int b    = blockIdx.y;

    // weights -> wsh (half): rows 0-31 theta, 32-63 phi, 64-95 origin
    for (int i = t; i < 2048; i += 128) {
        int r = i >> 6;
        int c = i & 63;
        wsh[r * WSTR + c]        = __float2half(w_th[i]);
        wsh[(32 + r) * WSTR + c] = __float2half(w_ph[i]);
        wsh[(64 + r) * WSTR + c] = __float2half(w_or[i]);
    }
    if (t < 32) {
        bias[t]      = b_th[t];
        bias[32 + t] = b_ph[t];
        bias[64 + t] = b_or[t];
    }

    // x tile -> xs32 (coalesced)
    const float* xb = xg + ((size_t)b * CI) * HW + hp * 128;
    #pragma unroll
    for (int c = 0; c < CI; ++c) {
        xs32[c * 128 + t] = xb[(size_t)c * HW + t];
    }
    __syncthreads();

    // transpose + convert: xsh[px][c]
    #pragma unroll
    for (int c = 0; c < CI; c += 2) {
        float lo = xs32[c * 128 + t];
        float hi = xs32[(c + 1) * 128 + t];
        *(__half2*)&xsh[t * XSTR + c] = __floats2half2_rn(lo, hi);
    }
    __syncthreads();

    // A fragments: warp px strip [warp*32, warp*32+31], 2 m-tiles x 4 k-steps
    unsigned aX[2][4][4];
    {
        int arow = lane & 15;
        int acol = (lane >> 4) << 3;
        unsigned base = smem_u32(xsh);
        #pragma unroll
        for (int mt = 0; mt < 2; ++mt) {
            #pragma unroll
            for (int k = 0; k < 4; ++k) {
                unsigned ad = base +
                    (((warp * 32 + mt * 16 + arow) * XSTR + k * 16 + acol) << 1);
                ldmx4(aX[mt][k][0], aX[mt][k][1], aX[mt][k][2], aX[mt][k][3], ad);
            }
        }
    }

    const int brow = ((lane >> 4) << 3) + (lane & 7);
    const int bcol = ((lane >> 3) & 1) << 3;
    const unsigned wshBase = smem_u32(wsh);

    #pragma unroll 1
    for (int g = 0; g < 3; ++g) {
        float cf[2][4][4];
        #pragma unroll
        for (int mt = 0; mt < 2; ++mt) {
            #pragma unroll
            for (int nt = 0; nt < 4; ++nt) {
                cf[mt][nt][0] = 0.f; cf[mt][nt][1] = 0.f;
                cf[mt][nt][2] = 0.f; cf[mt][nt][3] = 0.f;
            }
        }
        #pragma unroll
        for (int nt2 = 0; nt2 < 2; ++nt2) {
            #pragma unroll
            for (int k = 0; k < 4; ++k) {
                unsigned bw[4];
                unsigned ra = wshBase +
                    (((g * 32 + nt2 * 16 + brow) * WSTR + k * 16 + bcol) << 1);
                ldmx4(bw[0], bw[1], bw[2], bw[3], ra);
                mma16816(cf[0][nt2*2],   aX[0][k], &bw[0], cf[0][nt2*2]);
                mma16816(cf[0][nt2*2+1], aX[0][k], &bw[2], cf[0][nt2*2+1]);
                mma16816(cf[1][nt2*2],   aX[1][k], &bw[0], cf[1][nt2*2]);
                mma16816(cf[1][nt2*2+1], aX[1][k], &bw[2], cf[1][nt2*2+1]);
            }
        }
        // add bias
        #pragma unroll
        for (int mt = 0; mt < 2; ++mt) {
            #pragma unroll
            for (int nt = 0; nt < 4; ++nt) {
                int o0 = g * 32 + nt * 8 + (lane & 3) * 2;
                cf[mt][nt][0] += bias[o0];
                cf[mt][nt][1] += bias[o0 + 1];
                cf[mt][nt][2] += bias[o0];
                cf[mt][nt][3] += bias[o0 + 1];
            }
        }

        if (g == 0) {
            // theta -> Qh directly ([px][c] matches C layout)
            __half2* Qb = (__half2*)(Qh + ((size_t)b * HW + hp * 128) * CM);
            #pragma unroll
            for (int mt = 0; mt < 2; ++mt) {
                int row = warp * 32 + mt * 16 + (lane >> 2);
                #pragma unroll
                for (int nt = 0; nt < 4; ++nt) {
                    int cp = (nt * 8 + (lane & 3) * 2) >> 1;
                    Qb[row * 16 + cp]       = __floats2half2_rn(cf[mt][nt][0], cf[mt][nt][1]);
                    Qb[(row + 8) * 16 + cp] = __floats2half2_rn(cf[mt][nt][2], cf[mt][nt][3]);
                }
            }
        } else {
            // stage [px][o'] then 2x2 maxpool
            #pragma unroll
            for (int mt = 0; mt < 2; ++mt) {
                int row = warp * 32 + mt * 16 + (lane >> 2);
                #pragma unroll
                for (int nt = 0; nt < 4; ++nt) {
                    int c0 = nt * 8 + (lane & 3) * 2;
                    stg[row * 33 + c0]           = cf[mt][nt][0];
                    stg[row * 33 + c0 + 1]       = cf[mt][nt][1];
                    stg[(row + 8) * 33 + c0]     = cf[mt][nt][2];
                    stg[(row + 8) * 33 + c0 + 1] = cf[mt][nt][3];
                }
            }
            __syncthreads();
            if (g == 1) {
                #pragma unroll
                for (int i = 0; i < 8; ++i) {
                    int idx = t + i * 128;
                    int kw = idx >> 5;
                    int o  = idx & 31;
                    float mv = fmaxf(
                        fmaxf(stg[(2*kw) * 33 + o], stg[(2*kw + 1) * 33 + o]),
                        fmaxf(stg[(64 + 2*kw) * 33 + o], stg[(65 + 2*kw) * 33 + o]));
                    Kh[((size_t)b * NKV + hp * 32 + kw) * CM + o] = __float2half(mv);
                }
            } else {
                #pragma unroll
                for (int i = 0; i < 8; ++i) {
                    int idx = t + i * 128;
                    int o  = idx >> 5;
                    int kw = idx & 31;
                    float mv = fmaxf(
                        fmaxf(stg[(2*kw) * 33 + o], stg[(2*kw + 1) * 33 + o]),
                        fmaxf(stg[(64 + 2*kw) * 33 + o], stg[(65 + 2*kw) * 33 + o]));
                    Vth[((size_t)b * CM + o) * NKV + hp * 32 + kw] = __float2half(mv);
                }
            }
            __syncthreads();
        }
    }
}

// ---------------------------------------------------------------------------
// Kernel 2: attention via mma.sync, online softmax, cp.async double buffering.
// grid (32 q-tiles of 128, B), 256 threads = 8 warps (16 q rows each).
// ---------------------------------------------------------------------------
#define QSTR 40
#define VSTR 72

__global__ void __launch_bounds__(256) attn_kernel()
{
    __shared__ __half Qsm[128 * QSTR];
    __shared__ __half Ksm[2 * 64 * QSTR];
    __shared__ __half Vsm[2 * 32 * VSTR];
    __shared__ __half Ysm[128 * QSTR];

    const int t    = threadIdx.x;
    const int warp = t >> 5;
    const int lane = t & 31;
    const int b    = blockIdx.y;
    const int q0   = blockIdx.x * 128;

    // prologue: Q tile + chunk 0 of K/V via cp.async
    {
        #pragma unroll
        for (int i = 0; i < 2; ++i) {
            int idx = t + i * 256;
            int row = idx >> 2;
            int seg = idx & 3;
            CP_ASYNC16(smem_u32(&Qsm[row * QSTR + seg * 8]),
                       Qh + ((size_t)b * HW + q0 + row) * CM + seg * 8);
        }
        {
            int row = t >> 2;
            int seg = t & 3;
            CP_ASYNC16(smem_u32(&Ksm[row * QSTR + seg * 8]),
                       Kh + ((size_t)b * NKV + row) * CM + seg * 8);
        }
        {
            int row = t >> 3;
            int seg = t & 7;
            CP_ASYNC16(smem_u32(&Vsm[row * VSTR + seg * 8]),
                       Vth + ((size_t)b * CM + row) * NKV + seg * 8);
        }
        CP_COMMIT();
        CP_WAIT0();
        __syncthreads();
    }

    // A-operand (Q) fragments for 2 k-steps
    unsigned aQ0[4];
    unsigned aQ1[4];
    {
        int arow = lane & 15;
        int acol = (lane >> 4) << 3;
        unsigned base = smem_u32(Qsm);
        unsigned ad0 = base + (((warp * 16 + arow) * QSTR + acol) << 1);
        ldmx4(aQ0[0], aQ0[1], aQ0[2], aQ0[3], ad0);
        ldmx4(aQ1[0], aQ1[1], aQ1[2], aQ1[3], ad0 + 32);
    }

    const int brow = ((lane >> 4) << 3) + (lane & 7);
    const int bcol = ((lane >> 3) & 1) << 3;
    const unsigned ksBase = smem_u32(Ksm);
    const unsigned vsBase = smem_u32(Vsm);

    float oAcc[4][4];
    #pragma unroll
    for (int n = 0; n < 4; ++n) {
        oAcc[n][0] = 0.f; oAcc[n][1] = 0.f; oAcc[n][2] = 0.f; oAcc[n][3] = 0.f;
    }
    float m_lo = -1e30f;
    float m_hi = -1e30f;
    float l_lo = 0.f;
    float l_hi = 0.f;

    for (int kc = 0; kc < 16; ++kc) {
        const int cur = kc & 1;
        // prefetch next chunk into other buffer (overlaps with compute)
        if (kc < 15) {
            int nxt = cur ^ 1;
            {
                int row = t >> 2;
                int seg = t & 3;
                CP_ASYNC16(smem_u32(&Ksm[nxt * 64 * QSTR + row * QSTR + seg * 8]),
                           Kh + ((size_t)b * NKV + (kc + 1) * 64 + row) * CM + seg * 8);
            }
            {
                int row = t >> 3;
                int seg = t & 7;
                CP_ASYNC16(smem_u32(&Vsm[nxt * 32 * VSTR + row * VSTR + seg * 8]),
                           Vth + ((size_t)b * CM + row) * NKV + (kc + 1) * 64 + seg * 8);
            }
            CP_COMMIT();
        }
        const unsigned ksB = ksBase + cur * (64 * QSTR * 2);
        const unsigned vsB = vsBase + cur * (32 * VSTR * 2);

        // sAcc = Q K^T for this 64-kv chunk
        float sAcc[8][4];
        #pragma unroll
        for (int j = 0; j < 8; ++j) {
            sAcc[j][0] = 0.f; sAcc[j][1] = 0.f; sAcc[j][2] = 0.f; sAcc[j][3] = 0.f;
        }
        #pragma unroll
        for (int g = 0; g < 4; ++g) {
            unsigned bkf[4];
            unsigned ra = ksB + (((g * 16 + brow) * QSTR + bcol) << 1);
            ldmx4(bkf[0], bkf[1], bkf[2], bkf[3], ra);
            mma16816(sAcc[2*g],   aQ0, &bkf[0], sAcc[2*g]);
            mma16816(sAcc[2*g+1], aQ0, &bkf[2], sAcc[2*g+1]);
            ldmx4(bkf[0], bkf[1], bkf[2], bkf[3], ra + 32);
            mma16816(sAcc[2*g],   aQ1, &bkf[0], sAcc[2*g]);
            mma16816(sAcc[2*g+1], aQ1, &bkf[2], sAcc[2*g+1]);
        }

        // online softmax update
        float mlo = -1e30f;
        float mhi = -1e30f;
        #pragma unroll
        for (int j = 0; j < 8; ++j) {
            mlo = fmaxf(mlo, fmaxf(sAcc[j][0], sAcc[j][1]));
            mhi = fmaxf(mhi, fmaxf(sAcc[j][2], sAcc[j][3]));
        }
        mlo = fmaxf(mlo, __shfl_xor_sync(0xffffffffu, mlo, 1));
        mlo = fmaxf(mlo, __shfl_xor_sync(0xffffffffu, mlo, 2));
        mhi = fmaxf(mhi, __shfl_xor_sync(0xffffffffu, mhi, 1));
        mhi = fmaxf(mhi, __shfl_xor_sync(0xffffffffu, mhi, 2));
        float nmlo = fmaxf(m_lo, mlo);
        float nmhi = fmaxf(m_hi, mhi);
        float sclo = __expf(m_lo - nmlo);
        float schi = __expf(m_hi - nmhi);
        m_lo = nmlo;
        m_hi = nmhi;

        float slo = 0.f;
        float shi = 0.f;
        unsigned pPk[8][2];
        #pragma unroll
        for (int j = 0; j < 8; ++j) {
            float p0 = __expf(sAcc[j][0] - nmlo);
            float p1 = __expf(sAcc[j][1] - nmlo);
            float p2 = __expf(sAcc[j][2] - nmhi);
            float p3 = __expf(sAcc[j][3] - nmhi);
            slo += p0 + p1;
            shi += p2 + p3;
            pPk[j][0] = packh2(p0, p1);
            pPk[j][1] = packh2(p2, p3);
        }
        slo += __shfl_xor_sync(0xffffffffu, slo, 1);
        slo += __shfl_xor_sync(0xffffffffu, slo, 2);
        shi += __shfl_xor_sync(0xffffffffu, shi, 1);
        shi += __shfl_xor_sync(0xffffffffu, shi, 2);
        l_lo = l_lo * sclo + slo;
        l_hi = l_hi * schi + shi;
        #pragma unroll
        for (int n = 0; n < 4; ++n) {
            oAcc[n][0] *= sclo;
            oAcc[n][1] *= sclo;
            oAcc[n][2] *= schi;
            oAcc[n][3] *= schi;
        }

        // oAcc += P V
        #pragma unroll
        for (int s = 0; s < 4; ++s) {
            unsigned aP[4];
            aP[0] = pPk[2*s][0];
            aP[1] = pPk[2*s][1];
            aP[2] = pPk[2*s+1][0];
            aP[3] = pPk[2*s+1][1];
            #pragma unroll
            for (int pr = 0; pr < 2; ++pr) {
                unsigned bvf[4];
                unsigned rv = vsB + (((pr * 16 + brow) * VSTR + s * 16 + bcol) << 1);
                ldmx4(bvf[0], bvf[1], bvf[2], bvf[3], rv);
                mma16816(oAcc[2*pr],   aP, &bvf[0], oAcc[2*pr]);
                mma16816(oAcc[2*pr+1], aP, &bvf[2], oAcc[2*pr+1]);
            }
        }

        if (kc < 15) {
            CP_WAIT0();
            __syncthreads();
        }
    }

    // epilogue: normalize, stage as half, write Yh [q][c]
    {
        float ilo = 1.0f / l_lo;
        float ihi = 1.0f / l_hi;
        int rlo = warp * 16 + (lane >> 2);
        int cb  = (lane & 3) * 2;
        #pragma unroll
        for (int n = 0; n < 4; ++n) {
            int c = n * 8 + cb;
            *(__half2*)&Ysm[rlo * QSTR + c] =
                __floats2half2_rn(oAcc[n][0] * ilo, oAcc[n][1] * ilo);
            *(__half2*)&Ysm[(rlo + 8) * QSTR + c] =
                __floats2half2_rn(oAcc[n][2] * ihi, oAcc[n][3] * ihi);
        }
    }
    __syncthreads();
    {
        // 128 rows x 32 halfs = 512 uint4 segments (4 per row of 8 halfs each)
        #pragma unroll
        for (int i = 0; i < 2; ++i) {
            int idx = t + i * 256;
            int row = idx >> 2;
            int seg = idx & 3;
            *(uint4*)(Yh + ((size_t)b * HW + q0 + row) * CM + seg * 8) =
                *(uint4*)&Ysm[row * QSTR + seg * 8];
        }
    }
}

// ---------------------------------------------------------------------------
// Kernel 3: z = conv1x1(y, w_W) + b_W + x.  grid (16 tiles, B), 256 threads.
// fp32 SIMT (protects the error budget).
// ---------------------------------------------------------------------------
__global__ void __launch_bounds__(256) out_kernel(
    const float* __restrict__ xg, const float* __restrict__ w_W,
    const float* __restrict__ b_W, float* __restrict__ outg)
{
    __shared__ float ysm[256 * 33];
    __shared__ float ws[CI * CM];
    __shared__ float bsd[CI];

    const int t    = threadIdx.x;
    const int tile = blockIdx.x;
    const int b    = blockIdx.y;

    for (int i = t; i < CI * CM; i += 256) {
        ws[i] = w_W[i];
    }
    if (t < CI) {
        bsd[t] = b_W[t];
    }
    {
        const __half2* Yb = (const __half2*)(Yh + ((size_t)b * HW + tile * 256) * CM);
        #pragma unroll
        for (int i = 0; i < 16; ++i) {
            int idx = t + i * 256;
            int n  = idx >> 4;
            int cp = idx & 15;
            float2 f = __half22float2(Yb[n * 16 + cp]);
            ysm[n * 33 + 2 * cp]     = f.x;
            ysm[n * 33 + 2 * cp + 1] = f.y;
        }
    }
    __syncthreads();

    #pragma unroll
    for (int half = 0; half < 2; ++half) {
        float acc[32];
        #pragma unroll
        for (int o = 0; o < 32; ++o) {
            acc[o] = bsd[half * 32 + o];
        }
        #pragma unroll 4
        for (int c = 0; c < CM; c += 4) {
            float y0 = ysm[t * 33 + c];
            float y1 = ysm[t * 33 + c + 1];
            float y2 = ysm[t * 33 + c + 2];
            float y3 = ysm[t * 33 + c + 3];
            #pragma unroll
            for (int o = 0; o < 32; ++o) {
                float4 w4 = *(const float4*)&ws[(half * 32 + o) * CM + c];
                acc[o] += w4.x*y0 + w4.y*y1 + w4.z*y2 + w4.w*y3;
            }
        }
        #pragma unroll
        for (int o = 0; o < 32; ++o) {
            int co = half * 32 + o;
            size_t gi = ((size_t)b * CI + co) * HW + tile * 256 + t;
            outg[gi] = acc[o] + xg[gi];
        }
    }
}

// ---------------------------------------------------------------------------
extern "C" void kernel_launch(void* const* d_in, const int* in_sizes, int n_in,
                              void* d_out, int out_size)
{
    const float* xg   = (const float*)d_in[0];
    const float* w_or = (const float*)d_in[1];
    const float* b_or = (const float*)d_in[2];
    const float* w_th = (const float*)d_in[3];
    const float* b_th = (const float*)d_in[4];
    const float* w_ph = (const float*)d_in[5];
    const float* b_ph = (const float*)d_in[6];
    const float* w_W  = (const float*)d_in[7];
    const float* b_W  = (const float*)d_in[8];
    float* outg = (float*)d_out;

    cudaFuncSetAttribute(qkv_kernel, cudaFuncAttributeMaxDynamicSharedMemorySize,
                         SMEM1_BYTES);

    qkv_kernel<<<dim3(32, NB), 128, SMEM1_BYTES>>>(xg, w_or, b_or, w_th, b_th,
                                                   w_ph, b_ph);
    attn_kernel<<<dim3(32, NB), 256>>>();
    out_kernel<<<dim3(16, NB), 256>>>(xg, w_W, b_W, outg);
}

// round 6
// speedup vs baseline: 11.0500x; 1.2561x over previous
#include <cuda_runtime.h>
#include <cuda_fp16.h>

#define NB   16
#define CI   64
#define CM   32
#define HW   4096
#define NKV  1024

// Scratch (static device globals; no allocation allowed)
__device__ __half Qh[(size_t)NB * HW * CM];    // [B][4096 q][32 c]
__device__ __half Kh[(size_t)NB * NKV * CM];   // [B][1024 kv][32 c]
__device__ __half Vth[(size_t)NB * CM * NKV];  // [B][32 c][1024 kv]
__device__ __half Yh[(size_t)NB * HW * CM];    // [B][4096 q][32 c]

// ---------------------------------------------------------------------------
// helpers
// ---------------------------------------------------------------------------
__device__ __forceinline__ unsigned smem_u32(const void* p) {
    return (unsigned)__cvta_generic_to_shared(p);
}

__device__ __forceinline__ void ldmx4(unsigned& r0, unsigned& r1, unsigned& r2,
                                      unsigned& r3, unsigned addr) {
    asm volatile("ldmatrix.sync.aligned.m8n8.x4.shared.b16 {%0,%1,%2,%3}, [%4];\n"
                 : "=r"(r0), "=r"(r1), "=r"(r2), "=r"(r3) : "r"(addr));
}

__device__ __forceinline__ void mma16816(float* dd, const unsigned* aa,
                                         const unsigned* bb, const float* cc) {
    asm volatile(
        "mma.sync.aligned.m16n8k16.row.col.f32.f16.f16.f32 "
        "{%0,%1,%2,%3},{%4,%5,%6,%7},{%8,%9},{%10,%11,%12,%13};\n"
        : "=f"(dd[0]), "=f"(dd[1]), "=f"(dd[2]), "=f"(dd[3])
        : "r"(aa[0]), "r"(aa[1]), "r"(aa[2]), "r"(aa[3]),
          "r"(bb[0]), "r"(bb[1]),
          "f"(cc[0]), "f"(cc[1]), "f"(cc[2]), "f"(cc[3]));
}

__device__ __forceinline__ unsigned packh2(float av, float bv) {
    __half2 hh = __floats2half2_rn(av, bv);
    return *(unsigned*)&hh;
}

__device__ __forceinline__ unsigned ex2h2(unsigned in) {
    unsigned r;
    asm("ex2.approx.f16x2 %0, %1;\n" : "=r"(r) : "r"(in));
    return r;
}

#define CP_ASYNC16(sa, g) \
    asm volatile("cp.async.cg.shared.global [%0], [%1], 16;\n" :: "r"(sa), "l"(g))
#define CP_COMMIT() asm volatile("cp.async.commit_group;\n")
#define CP_WAIT0()  asm volatile("cp.async.wait_group 0;\n" ::: "memory")

#define L2E 1.4426950408889634f

// ---------------------------------------------------------------------------
// Kernel 1: qkv via tensor cores.
// grid (32 row-pairs, B), 128 threads = 4 warps.
// Direct float4 LDG -> half2 pack -> uint4 STS (no fp32 smem round-trip).
// ---------------------------------------------------------------------------
#define XSTR 72
#define WSTR 72
#define QKV_XSH   0
#define QKV_WSH   18432
#define QKV_STG   32256
#define QKV_BIAS  49152
#define SMEM1_BYTES (49152 + 384)

__global__ void __launch_bounds__(128) qkv_kernel(
    const float* __restrict__ xg,
    const float* __restrict__ w_or, const float* __restrict__ b_or,
    const float* __restrict__ w_th, const float* __restrict__ b_th,
    const float* __restrict__ w_ph, const float* __restrict__ b_ph)
{
    extern __shared__ char smraw[];
    __half* xsh  = (__half*)(smraw + QKV_XSH);    // [128 px][XSTR]
    __half* wsh  = (__half*)(smraw + QKV_WSH);    // [96 out][WSTR]
    float*  stg  = (float*)(smraw + QKV_STG);     // [128 px][33]
    float*  bias = (float*)(smraw + QKV_BIAS);    // [96]

    const int t    = threadIdx.x;
    const int warp = t >> 5;
    const int lane = t & 31;
    const int hp   = blockIdx.x;
    const int b    = blockIdx.y;

    // weights -> wsh (half): rows 0-31 theta, 32-63 phi, 64-95 origin
    for (int i = t; i < 2048; i += 128) {
        int r = i >> 6;
        int c = i & 63;
        wsh[r * WSTR + c]        = __float2half(w_th[i]);
        wsh[(32 + r) * WSTR + c] = __float2half(w_ph[i]);
        wsh[(64 + r) * WSTR + c] = __float2half(w_or[i]);
    }
    if (t < 32) {
        bias[t]      = b_th[t];
        bias[32 + t] = b_ph[t];
        bias[64 + t] = b_or[t];
    }

    // x tile: each thread loads 4 px x 16 ch as float4, packs to half, STS uint4
    {
        const int p0 = (t & 31) * 4;
        const int c0 = (t >> 5) * 16;
        const float* xb = xg + ((size_t)b * CI + c0) * HW + hp * 128 + p0;
        unsigned wbuf[4][8];
        #pragma unroll
        for (int cc = 0; cc < 8; ++cc) {
            float4 va = *(const float4*)(xb + (size_t)(2 * cc) * HW);
            float4 vb = *(const float4*)(xb + (size_t)(2 * cc + 1) * HW);
            wbuf[0][cc] = packh2(va.x, vb.x);
            wbuf[1][cc] = packh2(va.y, vb.y);
            wbuf[2][cc] = packh2(va.z, vb.z);
            wbuf[3][cc] = packh2(va.w, vb.w);
        }
        #pragma unroll
        for (int j = 0; j < 4; ++j) {
            uint4 u0;
            u0.x = wbuf[j][0]; u0.y = wbuf[j][1]; u0.z = wbuf[j][2]; u0.w = wbuf[j][3];
            uint4 u1;
            u1.x = wbuf[j][4]; u1.y = wbuf[j][5]; u1.z = wbuf[j][6]; u1.w = wbuf[j][7];
            *(uint4*)&xsh[(p0 + j) * XSTR + c0]     = u0;
            *(uint4*)&xsh[(p0 + j) * XSTR + c0 + 8] = u1;
        }
    }
    __syncthreads();

    // A fragments: warp px strip, 2 m-tiles x 4 k-steps
    unsigned aX[2][4][4];
    {
        int arow = lane & 15;
        int acol = (lane >> 4) << 3;
        unsigned base = smem_u32(xsh);
        #pragma unroll
        for (int mt = 0; mt < 2; ++mt) {
            #pragma unroll
            for (int k = 0; k < 4; ++k) {
                unsigned ad = base +
                    (((warp * 32 + mt * 16 + arow) * XSTR + k * 16 + acol) << 1);
                ldmx4(aX[mt][k][0], aX[mt][k][1], aX[mt][k][2], aX[mt][k][3], ad);
            }
        }
    }

    const int brow = ((lane >> 4) << 3) + (lane & 7);
    const int bcol = ((lane >> 3) & 1) << 3;
    const unsigned wshBase = smem_u32(wsh);

    #pragma unroll 1
    for (int g = 0; g < 3; ++g) {
        float cf[2][4][4];
        #pragma unroll
        for (int mt = 0; mt < 2; ++mt) {
            #pragma unroll
            for (int nt = 0; nt < 4; ++nt) {
                cf[mt][nt][0] = 0.f; cf[mt][nt][1] = 0.f;
                cf[mt][nt][2] = 0.f; cf[mt][nt][3] = 0.f;
            }
        }
        #pragma unroll
        for (int nt2 = 0; nt2 < 2; ++nt2) {
            #pragma unroll
            for (int k = 0; k < 4; ++k) {
                unsigned bw[4];
                unsigned ra = wshBase +
                    (((g * 32 + nt2 * 16 + brow) * WSTR + k * 16 + bcol) << 1);
                ldmx4(bw[0], bw[1], bw[2], bw[3], ra);
                mma16816(cf[0][nt2*2],   aX[0][k], &bw[0], cf[0][nt2*2]);
                mma16816(cf[0][nt2*2+1], aX[0][k], &bw[2], cf[0][nt2*2+1]);
                mma16816(cf[1][nt2*2],   aX[1][k], &bw[0], cf[1][nt2*2]);
                mma16816(cf[1][nt2*2+1], aX[1][k], &bw[2], cf[1][nt2*2+1]);
            }
        }
        // add bias
        #pragma unroll
        for (int mt = 0; mt < 2; ++mt) {
            #pragma unroll
            for (int nt = 0; nt < 4; ++nt) {
                int o0 = g * 32 + nt * 8 + (lane & 3) * 2;
                cf[mt][nt][0] += bias[o0];
                cf[mt][nt][1] += bias[o0 + 1];
                cf[mt][nt][2] += bias[o0];
                cf[mt][nt][3] += bias[o0 + 1];
            }
        }

        if (g == 0) {
            __half2* Qb = (__half2*)(Qh + ((size_t)b * HW + hp * 128) * CM);
            #pragma unroll
            for (int mt = 0; mt < 2; ++mt) {
                int row = warp * 32 + mt * 16 + (lane >> 2);
                #pragma unroll
                for (int nt = 0; nt < 4; ++nt) {
                    int cp = (nt * 8 + (lane & 3) * 2) >> 1;
                    Qb[row * 16 + cp]       = __floats2half2_rn(cf[mt][nt][0], cf[mt][nt][1]);
                    Qb[(row + 8) * 16 + cp] = __floats2half2_rn(cf[mt][nt][2], cf[mt][nt][3]);
                }
            }
        } else {
            #pragma unroll
            for (int mt = 0; mt < 2; ++mt) {
                int row = warp * 32 + mt * 16 + (lane >> 2);
                #pragma unroll
                for (int nt = 0; nt < 4; ++nt) {
                    int c0 = nt * 8 + (lane & 3) * 2;
                    stg[row * 33 + c0]           = cf[mt][nt][0];
                    stg[row * 33 + c0 + 1]       = cf[mt][nt][1];
                    stg[(row + 8) * 33 + c0]     = cf[mt][nt][2];
                    stg[(row + 8) * 33 + c0 + 1] = cf[mt][nt][3];
                }
            }
            __syncthreads();
            if (g == 1) {
                #pragma unroll
                for (int i = 0; i < 8; ++i) {
                    int idx = t + i * 128;
                    int kw = idx >> 5;
                    int o  = idx & 31;
                    float mv = fmaxf(
                        fmaxf(stg[(2*kw) * 33 + o], stg[(2*kw + 1) * 33 + o]),
                        fmaxf(stg[(64 + 2*kw) * 33 + o], stg[(65 + 2*kw) * 33 + o]));
                    Kh[((size_t)b * NKV + hp * 32 + kw) * CM + o] = __float2half(mv);
                }
            } else {
                #pragma unroll
                for (int i = 0; i < 8; ++i) {
                    int idx = t + i * 128;
                    int o  = idx >> 5;
                    int kw = idx & 31;
                    float mv = fmaxf(
                        fmaxf(stg[(2*kw) * 33 + o], stg[(2*kw + 1) * 33 + o]),
                        fmaxf(stg[(64 + 2*kw) * 33 + o], stg[(65 + 2*kw) * 33 + o]));
                    Vth[((size_t)b * CM + o) * NKV + hp * 32 + kw] = __float2half(mv);
                }
            }
            __syncthreads();
        }
    }
}

// ---------------------------------------------------------------------------
// Kernel 2: attention via mma.sync, online softmax (f16x2 ex2), cp.async DB.
// grid (32 q-tiles of 128, B), 256 threads = 8 warps.
// ---------------------------------------------------------------------------
#define QSTR 40
#define VSTR 72

__global__ void __launch_bounds__(256) attn_kernel()
{
    __shared__ __half Qsm[128 * QSTR];
    __shared__ __half Ksm[2 * 64 * QSTR];
    __shared__ __half Vsm[2 * 32 * VSTR];
    __shared__ __half Ysm[128 * QSTR];

    const int t    = threadIdx.x;
    const int warp = t >> 5;
    const int lane = t & 31;
    const int b    = blockIdx.y;
    const int q0   = blockIdx.x * 128;

    // prologue: Q tile + chunk 0 of K/V via cp.async
    {
        #pragma unroll
        for (int i = 0; i < 2; ++i) {
            int idx = t + i * 256;
            int row = idx >> 2;
            int seg = idx & 3;
            CP_ASYNC16(smem_u32(&Qsm[row * QSTR + seg * 8]),
                       Qh + ((size_t)b * HW + q0 + row) * CM + seg * 8);
        }
        {
            int row = t >> 2;
            int seg = t & 3;
            CP_ASYNC16(smem_u32(&Ksm[row * QSTR + seg * 8]),
                       Kh + ((size_t)b * NKV + row) * CM + seg * 8);
        }
        {
            int row = t >> 3;
            int seg = t & 7;
            CP_ASYNC16(smem_u32(&Vsm[row * VSTR + seg * 8]),
                       Vth + ((size_t)b * CM + row) * NKV + seg * 8);
        }
        CP_COMMIT();
        CP_WAIT0();
        __syncthreads();
    }

    // A-operand (Q) fragments for 2 k-steps
    unsigned aQ0[4];
    unsigned aQ1[4];
    {
        int arow = lane & 15;
        int acol = (lane >> 4) << 3;
        unsigned base = smem_u32(Qsm);
        unsigned ad0 = base + (((warp * 16 + arow) * QSTR + acol) << 1);
        ldmx4(aQ0[0], aQ0[1], aQ0[2], aQ0[3], ad0);
        ldmx4(aQ1[0], aQ1[1], aQ1[2], aQ1[3], ad0 + 32);
    }

    const int brow = ((lane >> 4) << 3) + (lane & 7);
    const int bcol = ((lane >> 3) & 1) << 3;
    const unsigned ksBase = smem_u32(Ksm);
    const unsigned vsBase = smem_u32(Vsm);

    float oAcc[4][4];
    #pragma unroll
    for (int n = 0; n < 4; ++n) {
        oAcc[n][0] = 0.f; oAcc[n][1] = 0.f; oAcc[n][2] = 0.f; oAcc[n][3] = 0.f;
    }
    float m_lo = -1e30f;
    float m_hi = -1e30f;
    float l_lo = 0.f;
    float l_hi = 0.f;

    for (int kc = 0; kc < 16; ++kc) {
        const int cur = kc & 1;
        if (kc < 15) {
            int nxt = cur ^ 1;
            {
                int row = t >> 2;
                int seg = t & 3;
                CP_ASYNC16(smem_u32(&Ksm[nxt * 64 * QSTR + row * QSTR + seg * 8]),
                           Kh + ((size_t)b * NKV + (kc + 1) * 64 + row) * CM + seg * 8);
            }
            {
                int row = t >> 3;
                int seg = t & 7;
                CP_ASYNC16(smem_u32(&Vsm[nxt * 32 * VSTR + row * VSTR + seg * 8]),
                           Vth + ((size_t)b * CM + row) * NKV + (kc + 1) * 64 + seg * 8);
            }
            CP_COMMIT();
        }
        const unsigned ksB = ksBase + cur * (64 * QSTR * 2);
        const unsigned vsB = vsBase + cur * (32 * VSTR * 2);

        // sAcc = Q K^T for this 64-kv chunk
        float sAcc[8][4];
        #pragma unroll
        for (int j = 0; j < 8; ++j) {
            sAcc[j][0] = 0.f; sAcc[j][1] = 0.f; sAcc[j][2] = 0.f; sAcc[j][3] = 0.f;
        }
        #pragma unroll
        for (int g = 0; g < 4; ++g) {
            unsigned bkf[4];
            unsigned ra = ksB + (((g * 16 + brow) * QSTR + bcol) << 1);
            ldmx4(bkf[0], bkf[1], bkf[2], bkf[3], ra);
            mma16816(sAcc[2*g],   aQ0, &bkf[0], sAcc[2*g]);
            mma16816(sAcc[2*g+1], aQ0, &bkf[2], sAcc[2*g+1]);
            ldmx4(bkf[0], bkf[1], bkf[2], bkf[3], ra + 32);
            mma16816(sAcc[2*g],   aQ1, &bkf[0], sAcc[2*g]);
            mma16816(sAcc[2*g+1], aQ1, &bkf[2], sAcc[2*g+1]);
        }

        // online softmax update
        float mlo = -1e30f;
        float mhi = -1e30f;
        #pragma unroll
        for (int j = 0; j < 8; ++j) {
            mlo = fmaxf(mlo, fmaxf(sAcc[j][0], sAcc[j][1]));
            mhi = fmaxf(mhi, fmaxf(sAcc[j][2], sAcc[j][3]));
        }
        mlo = fmaxf(mlo, __shfl_xor_sync(0xffffffffu, mlo, 1));
        mlo = fmaxf(mlo, __shfl_xor_sync(0xffffffffu, mlo, 2));
        mhi = fmaxf(mhi, __shfl_xor_sync(0xffffffffu, mhi, 1));
        mhi = fmaxf(mhi, __shfl_xor_sync(0xffffffffu, mhi, 2));
        float nmlo = fmaxf(m_lo, mlo);
        float nmhi = fmaxf(m_hi, mhi);
        float sclo = __expf(m_lo - nmlo);
        float schi = __expf(m_hi - nmhi);
        m_lo = nmlo;
        m_hi = nmhi;

        // P = exp(s - m) computed directly in fp16x2 via ex2.approx.f16x2
        const float mlo2 = nmlo * L2E;
        const float mhi2 = nmhi * L2E;
        float slo = 0.f;
        float shi = 0.f;
        unsigned pPk[8][2];
        #pragma unroll
        for (int j = 0; j < 8; ++j) {
            float e0 = fmaf(sAcc[j][0], L2E, -mlo2);
            float e1 = fmaf(sAcc[j][1], L2E, -mlo2);
            float e2 = fmaf(sAcc[j][2], L2E, -mhi2);
            float e3 = fmaf(sAcc[j][3], L2E, -mhi2);
            unsigned plo = ex2h2(packh2(e0, e1));
            unsigned phi = ex2h2(packh2(e2, e3));
            pPk[j][0] = plo;
            pPk[j][1] = phi;
            float2 flo = __half22float2(*(__half2*)&plo);
            float2 fhi = __half22float2(*(__half2*)&phi);
            slo += flo.x + flo.y;
            shi += fhi.x + fhi.y;
        }
        slo += __shfl_xor_sync(0xffffffffu, slo, 1);
        slo += __shfl_xor_sync(0xffffffffu, slo, 2);
        shi += __shfl_xor_sync(0xffffffffu, shi, 1);
        shi += __shfl_xor_sync(0xffffffffu, shi, 2);
        l_lo = l_lo * sclo + slo;
        l_hi = l_hi * schi + shi;
        #pragma unroll
        for (int n = 0; n < 4; ++n) {
            oAcc[n][0] *= sclo;
            oAcc[n][1] *= sclo;
            oAcc[n][2] *= schi;
            oAcc[n][3] *= schi;
        }

        // oAcc += P V
        #pragma unroll
        for (int s = 0; s < 4; ++s) {
            unsigned aP[4];
            aP[0] = pPk[2*s][0];
            aP[1] = pPk[2*s][1];
            aP[2] = pPk[2*s+1][0];
            aP[3] = pPk[2*s+1][1];
            #pragma unroll
            for (int pr = 0; pr < 2; ++pr) {
                unsigned bvf[4];
                unsigned rv = vsB + (((pr * 16 + brow) * VSTR + s * 16 + bcol) << 1);
                ldmx4(bvf[0], bvf[1], bvf[2], bvf[3], rv);
                mma16816(oAcc[2*pr],   aP, &bvf[0], oAcc[2*pr]);
                mma16816(oAcc[2*pr+1], aP, &bvf[2], oAcc[2*pr+1]);
            }
        }

        if (kc < 15) {
            CP_WAIT0();
            __syncthreads();
        }
    }

    // epilogue: normalize, stage as half, write Yh [q][c]
    {
        float ilo = 1.0f / l_lo;
        float ihi = 1.0f / l_hi;
        int rlo = warp * 16 + (lane >> 2);
        int cb  = (lane & 3) * 2;
        #pragma unroll
        for (int n = 0; n < 4; ++n) {
            int c = n * 8 + cb;
            *(__half2*)&Ysm[rlo * QSTR + c] =
                __floats2half2_rn(oAcc[n][0] * ilo, oAcc[n][1] * ilo);
            *(__half2*)&Ysm[(rlo + 8) * QSTR + c] =
                __floats2half2_rn(oAcc[n][2] * ihi, oAcc[n][3] * ihi);
        }
    }
    __syncthreads();
    {
        #pragma unroll
        for (int i = 0; i < 2; ++i) {
            int idx = t + i * 256;
            int row = idx >> 2;
            int seg = idx & 3;
            *(uint4*)(Yh + ((size_t)b * HW + q0 + row) * CM + seg * 8) =
                *(uint4*)&Ysm[row * QSTR + seg * 8];
        }
    }
}

// ---------------------------------------------------------------------------
// Kernel 3: z = conv1x1(y, w_W) + b_W + x via tensor cores.
// grid (32 px-tiles of 128, B), 256 threads = 8 warps (16 px each).
// ---------------------------------------------------------------------------
#define OUT_YSM  0
#define OUT_WSM  10240
#define OUT_BSD  15360
#define OUT_OSM  15616
#define OSTR     132
#define SMEM3_BYTES (15616 + 64 * OSTR * 4)

__global__ void __launch_bounds__(256) out_kernel(
    const float* __restrict__ xg, const float* __restrict__ w_W,
    const float* __restrict__ b_W, float* __restrict__ outg)
{
    extern __shared__ char osraw[];
    __half* ysm = (__half*)(osraw + OUT_YSM);   // [128 px][QSTR]
    __half* wsm = (__half*)(osraw + OUT_WSM);   // [64 out][QSTR]
    float*  bsd = (float*)(osraw + OUT_BSD);    // [64]
    float*  osm = (float*)(osraw + OUT_OSM);    // [64 out][OSTR px]

    const int t    = threadIdx.x;
    const int warp = t >> 5;
    const int lane = t & 31;
    const int tile = blockIdx.x;
    const int b    = blockIdx.y;

    // load y tile (half): 128 rows x 32 halfs = 512 uint4
    {
        #pragma unroll
        for (int i = 0; i < 2; ++i) {
            int idx = t + i * 256;
            int row = idx >> 2;
            int seg = idx & 3;
            *(uint4*)&ysm[row * QSTR + seg * 8] =
                *(const uint4*)(Yh + ((size_t)b * HW + tile * 128 + row) * CM + seg * 8);
        }
    }
    // weights -> half
    for (int i = t; i < 2048; i += 256) {
        wsm[(i >> 5) * QSTR + (i & 31)] = __float2half(w_W[i]);
    }
    if (t < 64) {
        bsd[t] = b_W[t];
    }
    __syncthreads();

    // A fragments (y): 16 px rows per warp, k=32 -> 2 k-steps
    unsigned aY0[4];
    unsigned aY1[4];
    {
        int arow = lane & 15;
        int acol = (lane >> 4) << 3;
        unsigned base = smem_u32(ysm);
        unsigned ad = base + (((warp * 16 + arow) * QSTR + acol) << 1);
        ldmx4(aY0[0], aY0[1], aY0[2], aY0[3], ad);
        ldmx4(aY1[0], aY1[1], aY1[2], aY1[3], ad + 32);
    }

    const int brow = ((lane >> 4) << 3) + (lane & 7);
    const int bcol = ((lane >> 3) & 1) << 3;
    const unsigned wBase = smem_u32(wsm);

    float cf[8][4];
    #pragma unroll
    for (int nt = 0; nt < 8; ++nt) {
        cf[nt][0] = 0.f; cf[nt][1] = 0.f; cf[nt][2] = 0.f; cf[nt][3] = 0.f;
    }
    #pragma unroll
    for (int g = 0; g < 4; ++g) {
        unsigned bw[4];
        unsigned ra = wBase + (((g * 16 + brow) * QSTR + bcol) << 1);
        ldmx4(bw[0], bw[1], bw[2], bw[3], ra);
        mma16816(cf[2*g],   aY0, &bw[0], cf[2*g]);
        mma16816(cf[2*g+1], aY0, &bw[2], cf[2*g+1]);
        ldmx4(bw[0], bw[1], bw[2], bw[3], ra + 32);
        mma16816(cf[2*g],   aY1, &bw[0], cf[2*g]);
        mma16816(cf[2*g+1], aY1, &bw[2], cf[2*g+1]);
    }

    // stage to osm[out][px] with bias
    {
        int rlo = warp * 16 + (lane >> 2);
        int cb  = (lane & 3) * 2;
        #pragma unroll
        for (int nt = 0; nt < 8; ++nt) {
            int c = nt * 8 + cb;
            float bc0 = bsd[c];
            float bc1 = bsd[c + 1];
            osm[c * OSTR + rlo]           = cf[nt][0] + bc0;
            osm[(c + 1) * OSTR + rlo]     = cf[nt][1] + bc1;
            osm[c * OSTR + rlo + 8]       = cf[nt][2] + bc0;
            osm[(c + 1) * OSTR + rlo + 8] = cf[nt][3] + bc1;
        }
    }
    __syncthreads();

    // residual add + store: 128 px x 64 out = 2048 float4
    {
        #pragma unroll
        for (int i = 0; i < 8; ++i) {
            int idx = t + i * 256;
            int co = idx >> 5;
            int p4 = idx & 31;
            float4 yv = *(const float4*)&osm[co * OSTR + p4 * 4];
            size_t gi = ((size_t)b * CI + co) * HW + tile * 128 + p4 * 4;
            float4 xv = *(const float4*)&xg[gi];
            float4 ov;
            ov.x = yv.x + xv.x;
            ov.y = yv.y + xv.y;
            ov.z = yv.z + xv.z;
            ov.w = yv.w + xv.w;
            *(float4*)&outg[gi] = ov;
        }
    }
}

// ---------------------------------------------------------------------------
extern "C" void kernel_launch(void* const* d_in, const int* in_sizes, int n_in,
                              void* d_out, int out_size)
{
    const float* xg   = (const float*)d_in[0];
    const float* w_or = (const float*)d_in[1];
    const float* b_or = (const float*)d_in[2];
    const float* w_th = (const float*)d_in[3];
    const float* b_th = (const float*)d_in[4];
    const float* w_ph = (const float*)d_in[5];
    const float* b_ph = (const float*)d_in[6];
    const float* w_W  = (const float*)d_in[7];
    const float* b_W  = (const float*)d_in[8];
    float* outg = (float*)d_out;

    cudaFuncSetAttribute(qkv_kernel, cudaFuncAttributeMaxDynamicSharedMemorySize,
                         SMEM1_BYTES);
    cudaFuncSetAttribute(out_kernel, cudaFuncAttributeMaxDynamicSharedMemorySize,
                         SMEM3_BYTES);

    qkv_kernel<<<dim3(32, NB), 128, SMEM1_BYTES>>>(xg, w_or, b_or, w_th, b_th,
                                                   w_ph, b_ph);
    attn_kernel<<<dim3(32, NB), 256>>>();
    out_kernel<<<dim3(32, NB), 256, SMEM3_BYTES>>>(xg, w_W, b_W, outg);
}

// round 7
// speedup vs baseline: 11.4155x; 1.0331x over previous
#include <cuda_runtime.h>
#include <cuda_fp16.h>

#define NB   16
#define CI   64
#define CM   32
#define HW   4096
#define NKV  1024

// Scratch (static device globals; no allocation allowed)
__device__ __half Qh[(size_t)NB * HW * CM];    // [B][4096 q][32 c]
__device__ __half Kh[(size_t)NB * NKV * CM];   // [B][1024 kv][32 c]
__device__ __half Vth[(size_t)NB * CM * NKV];  // [B][32 c][1024 kv]
__device__ __half Yh[(size_t)NB * HW * CM];    // [B][4096 q][32 c]

// ---------------------------------------------------------------------------
// helpers
// ---------------------------------------------------------------------------
__device__ __forceinline__ unsigned smem_u32(const void* p) {
    return (unsigned)__cvta_generic_to_shared(p);
}

__device__ __forceinline__ void ldmx4(unsigned& r0, unsigned& r1, unsigned& r2,
                                      unsigned& r3, unsigned addr) {
    asm volatile("ldmatrix.sync.aligned.m8n8.x4.shared.b16 {%0,%1,%2,%3}, [%4];\n"
                 : "=r"(r0), "=r"(r1), "=r"(r2), "=r"(r3) : "r"(addr));
}

__device__ __forceinline__ void mma16816(float* dd, const unsigned* aa,
                                         const unsigned* bb, const float* cc) {
    asm volatile(
        "mma.sync.aligned.m16n8k16.row.col.f32.f16.f16.f32 "
        "{%0,%1,%2,%3},{%4,%5,%6,%7},{%8,%9},{%10,%11,%12,%13};\n"
        : "=f"(dd[0]), "=f"(dd[1]), "=f"(dd[2]), "=f"(dd[3])
        : "r"(aa[0]), "r"(aa[1]), "r"(aa[2]), "r"(aa[3]),
          "r"(bb[0]), "r"(bb[1]),
          "f"(cc[0]), "f"(cc[1]), "f"(cc[2]), "f"(cc[3]));
}

__device__ __forceinline__ unsigned packh2(float av, float bv) {
    __half2 hh = __floats2half2_rn(av, bv);
    return *(unsigned*)&hh;
}

__device__ __forceinline__ unsigned ex2h2(unsigned in) {
    unsigned r;
    asm("ex2.approx.f16x2 %0, %1;\n" : "=r"(r) : "r"(in));
    return r;
}

#define CP_ASYNC16(sa, g) \
    asm volatile("cp.async.cg.shared.global [%0], [%1], 16;\n" :: "r"(sa), "l"(g))
#define CP_COMMIT() asm volatile("cp.async.commit_group;\n")
#define CP_WAIT0()  asm volatile("cp.async.wait_group 0;\n" ::: "memory")

#define L2E 1.4426950408889634f

// ---------------------------------------------------------------------------
// Kernel 1: qkv via tensor cores.
// grid (32 row-pairs, B), 128 threads = 4 warps.
// stg aliases xsh (dead after A-fragments load) -> smem 31.9 KB.
// ---------------------------------------------------------------------------
#define XSTR 72
#define WSTR 72
#define QKV_XSH   0
#define QKV_WSH   18432
#define QKV_BIAS  32256
#define SMEM1_BYTES (32256 + 384)

__global__ void __launch_bounds__(128) qkv_kernel(
    const float* __restrict__ xg,
    const float* __restrict__ w_or, const float* __restrict__ b_or,
    const float* __restrict__ w_th, const float* __restrict__ b_th,
    const float* __restrict__ w_ph, const float* __restrict__ b_ph)
{
    extern __shared__ char smraw[];
    __half* xsh  = (__half*)(smraw + QKV_XSH);    // [128 px][XSTR]
    __half* wsh  = (__half*)(smraw + QKV_WSH);    // [96 out][WSTR]
    float*  bias = (float*)(smraw + QKV_BIAS);    // [96]
    float*  stg  = (float*)(smraw + QKV_XSH);     // alias: [128 px][33] fp32

    const int t    = threadIdx.x;
    const int warp = t >> 5;
    const int lane = t & 31;
    const int hp   = blockIdx.x;
    const int b    = blockIdx.y;

    // weights -> wsh (half): rows 0-31 theta, 32-63 phi, 64-95 origin
    for (int i = t; i < 2048; i += 128) {
        int r = i >> 6;
        int c = i & 63;
        wsh[r * WSTR + c]        = __float2half(w_th[i]);
        wsh[(32 + r) * WSTR + c] = __float2half(w_ph[i]);
        wsh[(64 + r) * WSTR + c] = __float2half(w_or[i]);
    }
    if (t < 32) {
        bias[t]      = b_th[t];
        bias[32 + t] = b_ph[t];
        bias[64 + t] = b_or[t];
    }

    // x tile: each thread loads 4 px x 16 ch as float4, packs to half, STS uint4
    {
        const int p0 = (t & 31) * 4;
        const int c0 = (t >> 5) * 16;
        const float* xb = xg + ((size_t)b * CI + c0) * HW + hp * 128 + p0;
        unsigned wbuf[4][8];
        #pragma unroll
        for (int cc = 0; cc < 8; ++cc) {
            float4 va = *(const float4*)(xb + (size_t)(2 * cc) * HW);
            float4 vb = *(const float4*)(xb + (size_t)(2 * cc + 1) * HW);
            wbuf[0][cc] = packh2(va.x, vb.x);
            wbuf[1][cc] = packh2(va.y, vb.y);
            wbuf[2][cc] = packh2(va.z, vb.z);
            wbuf[3][cc] = packh2(va.w, vb.w);
        }
        #pragma unroll
        for (int j = 0; j < 4; ++j) {
            uint4 u0;
            u0.x = wbuf[j][0]; u0.y = wbuf[j][1]; u0.z = wbuf[j][2]; u0.w = wbuf[j][3];
            uint4 u1;
            u1.x = wbuf[j][4]; u1.y = wbuf[j][5]; u1.z = wbuf[j][6]; u1.w = wbuf[j][7];
            *(uint4*)&xsh[(p0 + j) * XSTR + c0]     = u0;
            *(uint4*)&xsh[(p0 + j) * XSTR + c0 + 8] = u1;
        }
    }
    __syncthreads();

    // A fragments: warp px strip, 2 m-tiles x 4 k-steps
    unsigned aX[2][4][4];
    {
        int arow = lane & 15;
        int acol = (lane >> 4) << 3;
        unsigned base = smem_u32(xsh);
        #pragma unroll
        for (int mt = 0; mt < 2; ++mt) {
            #pragma unroll
            for (int k = 0; k < 4; ++k) {
                unsigned ad = base +
                    (((warp * 32 + mt * 16 + arow) * XSTR + k * 16 + acol) << 1);
                ldmx4(aX[mt][k][0], aX[mt][k][1], aX[mt][k][2], aX[mt][k][3], ad);
            }
        }
    }
    __syncthreads();   // xsh is now dead; stg may overwrite it

    const int brow = ((lane >> 4) << 3) + (lane & 7);
    const int bcol = ((lane >> 3) & 1) << 3;
    const unsigned wshBase = smem_u32(wsh);

    #pragma unroll 1
    for (int g = 0; g < 3; ++g) {
        float cf[2][4][4];
        #pragma unroll
        for (int mt = 0; mt < 2; ++mt) {
            #pragma unroll
            for (int nt = 0; nt < 4; ++nt) {
                cf[mt][nt][0] = 0.f; cf[mt][nt][1] = 0.f;
                cf[mt][nt][2] = 0.f; cf[mt][nt][3] = 0.f;
            }
        }
        #pragma unroll
        for (int nt2 = 0; nt2 < 2; ++nt2) {
            #pragma unroll
            for (int k = 0; k < 4; ++k) {
                unsigned bw[4];
                unsigned ra = wshBase +
                    (((g * 32 + nt2 * 16 + brow) * WSTR + k * 16 + bcol) << 1);
                ldmx4(bw[0], bw[1], bw[2], bw[3], ra);
                mma16816(cf[0][nt2*2],   aX[0][k], &bw[0], cf[0][nt2*2]);
                mma16816(cf[0][nt2*2+1], aX[0][k], &bw[2], cf[0][nt2*2+1]);
                mma16816(cf[1][nt2*2],   aX[1][k], &bw[0], cf[1][nt2*2]);
                mma16816(cf[1][nt2*2+1], aX[1][k], &bw[2], cf[1][nt2*2+1]);
            }
        }
        // add bias
        #pragma unroll
        for (int mt = 0; mt < 2; ++mt) {
            #pragma unroll
            for (int nt = 0; nt < 4; ++nt) {
                int o0 = g * 32 + nt * 8 + (lane & 3) * 2;
                cf[mt][nt][0] += bias[o0];
                cf[mt][nt][1] += bias[o0 + 1];
                cf[mt][nt][2] += bias[o0];
                cf[mt][nt][3] += bias[o0 + 1];
            }
        }

        if (g == 0) {
            __half2* Qb = (__half2*)(Qh + ((size_t)b * HW + hp * 128) * CM);
            #pragma unroll
            for (int mt = 0; mt < 2; ++mt) {
                int row = warp * 32 + mt * 16 + (lane >> 2);
                #pragma unroll
                for (int nt = 0; nt < 4; ++nt) {
                    int cp = (nt * 8 + (lane & 3) * 2) >> 1;
                    Qb[row * 16 + cp]       = __floats2half2_rn(cf[mt][nt][0], cf[mt][nt][1]);
                    Qb[(row + 8) * 16 + cp] = __floats2half2_rn(cf[mt][nt][2], cf[mt][nt][3]);
                }
            }
        } else {
            #pragma unroll
            for (int mt = 0; mt < 2; ++mt) {
                int row = warp * 32 + mt * 16 + (lane >> 2);
                #pragma unroll
                for (int nt = 0; nt < 4; ++nt) {
                    int c0 = nt * 8 + (lane & 3) * 2;
                    stg[row * 33 + c0]           = cf[mt][nt][0];
                    stg[row * 33 + c0 + 1]       = cf[mt][nt][1];
                    stg[(row + 8) * 33 + c0]     = cf[mt][nt][2];
                    stg[(row + 8) * 33 + c0 + 1] = cf[mt][nt][3];
                }
            }
            __syncthreads();
            if (g == 1) {
                #pragma unroll
                for (int i = 0; i < 8; ++i) {
                    int idx = t + i * 128;
                    int kw = idx >> 5;
                    int o  = idx & 31;
                    float mv = fmaxf(
                        fmaxf(stg[(2*kw) * 33 + o], stg[(2*kw + 1) * 33 + o]),
                        fmaxf(stg[(64 + 2*kw) * 33 + o], stg[(65 + 2*kw) * 33 + o]));
                    Kh[((size_t)b * NKV + hp * 32 + kw) * CM + o] = __float2half(mv);
                }
            } else {
                #pragma unroll
                for (int i = 0; i < 8; ++i) {
                    int idx = t + i * 128;
                    int o  = idx >> 5;
                    int kw = idx & 31;
                    float mv = fmaxf(
                        fmaxf(stg[(2*kw) * 33 + o], stg[(2*kw + 1) * 33 + o]),
                        fmaxf(stg[(64 + 2*kw) * 33 + o], stg[(65 + 2*kw) * 33 + o]));
                    Vth[((size_t)b * CM + o) * NKV + hp * 32 + kw] = __float2half(mv);
                }
            }
            __syncthreads();
        }
    }
}

// ---------------------------------------------------------------------------
// Kernel 2: attention via mma.sync, online softmax (f16x2 ex2), cp.async DB.
// grid (32 q-tiles of 128, B), 256 threads = 8 warps.
// Ysm aliases Qsm (dead after prologue). Lane-local l partials (no per-iter
// sum shuffles); packed half2 max reduction (2 shuffles/iter).
// ---------------------------------------------------------------------------
#define QSTR 40
#define VSTR 72

__global__ void __launch_bounds__(256) attn_kernel()
{
    __shared__ __half Qsm[128 * QSTR];          // also Ysm in epilogue
    __shared__ __half Ksm[2 * 64 * QSTR];
    __shared__ __half Vsm[2 * 32 * VSTR];
    __half* Ysm = Qsm;

    const int t    = threadIdx.x;
    const int warp = t >> 5;
    const int lane = t & 31;
    const int b    = blockIdx.y;
    const int q0   = blockIdx.x * 128;

    // prologue: Q tile + chunk 0 of K/V via cp.async
    {
        #pragma unroll
        for (int i = 0; i < 2; ++i) {
            int idx = t + i * 256;
            int row = idx >> 2;
            int seg = idx & 3;
            CP_ASYNC16(smem_u32(&Qsm[row * QSTR + seg * 8]),
                       Qh + ((size_t)b * HW + q0 + row) * CM + seg * 8);
        }
        {
            int row = t >> 2;
            int seg = t & 3;
            CP_ASYNC16(smem_u32(&Ksm[row * QSTR + seg * 8]),
                       Kh + ((size_t)b * NKV + row) * CM + seg * 8);
        }
        {
            int row = t >> 3;
            int seg = t & 7;
            CP_ASYNC16(smem_u32(&Vsm[row * VSTR + seg * 8]),
                       Vth + ((size_t)b * CM + row) * NKV + seg * 8);
        }
        CP_COMMIT();
        CP_WAIT0();
        __syncthreads();
    }

    // A-operand (Q) fragments for 2 k-steps
    unsigned aQ0[4];
    unsigned aQ1[4];
    {
        int arow = lane & 15;
        int acol = (lane >> 4) << 3;
        unsigned base = smem_u32(Qsm);
        unsigned ad0 = base + (((warp * 16 + arow) * QSTR + acol) << 1);
        ldmx4(aQ0[0], aQ0[1], aQ0[2], aQ0[3], ad0);
        ldmx4(aQ1[0], aQ1[1], aQ1[2], aQ1[3], ad0 + 32);
    }

    const int brow = ((lane >> 4) << 3) + (lane & 7);
    const int bcol = ((lane >> 3) & 1) << 3;
    const unsigned ksBase = smem_u32(Ksm);
    const unsigned vsBase = smem_u32(Vsm);

    float oAcc[4][4];
    #pragma unroll
    for (int n = 0; n < 4; ++n) {
        oAcc[n][0] = 0.f; oAcc[n][1] = 0.f; oAcc[n][2] = 0.f; oAcc[n][3] = 0.f;
    }
    float m_lo = -1e30f;
    float m_hi = -1e30f;
    float l_lo = 0.f;   // lane-local partial; quad-reduced after the loop
    float l_hi = 0.f;

    for (int kc = 0; kc < 16; ++kc) {
        const int cur = kc & 1;
        if (kc < 15) {
            int nxt = cur ^ 1;
            {
                int row = t >> 2;
                int seg = t & 3;
                CP_ASYNC16(smem_u32(&Ksm[nxt * 64 * QSTR + row * QSTR + seg * 8]),
                           Kh + ((size_t)b * NKV + (kc + 1) * 64 + row) * CM + seg * 8);
            }
            {
                int row = t >> 3;
                int seg = t & 7;
                CP_ASYNC16(smem_u32(&Vsm[nxt * 32 * VSTR + row * VSTR + seg * 8]),
                           Vth + ((size_t)b * CM + row) * NKV + (kc + 1) * 64 + seg * 8);
            }
            CP_COMMIT();
        }
        const unsigned ksB = ksBase + cur * (64 * QSTR * 2);
        const unsigned vsB = vsBase + cur * (32 * VSTR * 2);

        // sAcc = Q K^T for this 64-kv chunk
        float sAcc[8][4];
        #pragma unroll
        for (int j = 0; j < 8; ++j) {
            sAcc[j][0] = 0.f; sAcc[j][1] = 0.f; sAcc[j][2] = 0.f; sAcc[j][3] = 0.f;
        }
        #pragma unroll
        for (int g = 0; g < 4; ++g) {
            unsigned bkf[4];
            unsigned ra = ksB + (((g * 16 + brow) * QSTR + bcol) << 1);
            ldmx4(bkf[0], bkf[1], bkf[2], bkf[3], ra);
            mma16816(sAcc[2*g],   aQ0, &bkf[0], sAcc[2*g]);
            mma16816(sAcc[2*g+1], aQ0, &bkf[2], sAcc[2*g+1]);
            ldmx4(bkf[0], bkf[1], bkf[2], bkf[3], ra + 32);
            mma16816(sAcc[2*g],   aQ1, &bkf[0], sAcc[2*g]);
            mma16816(sAcc[2*g+1], aQ1, &bkf[2], sAcc[2*g+1]);
        }

        // online softmax: packed half2 max reduce (2 shuffles)
        float mlo = -1e30f;
        float mhi = -1e30f;
        #pragma unroll
        for (int j = 0; j < 8; ++j) {
            mlo = fmaxf(mlo, fmaxf(sAcc[j][0], sAcc[j][1]));
            mhi = fmaxf(mhi, fmaxf(sAcc[j][2], sAcc[j][3]));
        }
        {
            unsigned mp = packh2(mlo, mhi);
            __half2 mh = *(__half2*)&mp;
            unsigned ms1 = __shfl_xor_sync(0xffffffffu, mp, 1);
            mh = __hmax2(mh, *(__half2*)&ms1);
            unsigned mhu = *(unsigned*)&mh;
            unsigned ms2 = __shfl_xor_sync(0xffffffffu, mhu, 2);
            mh = __hmax2(mh, *(__half2*)&ms2);
            mlo = __low2float(mh);
            mhi = __high2float(mh);
        }
        float nmlo = fmaxf(m_lo, mlo);
        float nmhi = fmaxf(m_hi, mhi);
        float sclo = __expf(m_lo - nmlo);
        float schi = __expf(m_hi - nmhi);
        m_lo = nmlo;
        m_hi = nmhi;

        // P = exp(s - m) in fp16x2 via ex2.approx.f16x2; lane-local sums
        const float mlo2 = nmlo * L2E;
        const float mhi2 = nmhi * L2E;
        float slo = 0.f;
        float shi = 0.f;
        unsigned pPk[8][2];
        #pragma unroll
        for (int j = 0; j < 8; ++j) {
            float e0 = fmaf(sAcc[j][0], L2E, -mlo2);
            float e1 = fmaf(sAcc[j][1], L2E, -mlo2);
            float e2 = fmaf(sAcc[j][2], L2E, -mhi2);
            float e3 = fmaf(sAcc[j][3], L2E, -mhi2);
            unsigned plo = ex2h2(packh2(e0, e1));
            unsigned phi = ex2h2(packh2(e2, e3));
            pPk[j][0] = plo;
            pPk[j][1] = phi;
            float2 flo = __half22float2(*(__half2*)&plo);
            float2 fhi = __half22float2(*(__half2*)&phi);
            slo += flo.x + flo.y;
            shi += fhi.x + fhi.y;
        }
        l_lo = l_lo * sclo + slo;
        l_hi = l_hi * schi + shi;
        #pragma unroll
        for (int n = 0; n < 4; ++n) {
            oAcc[n][0] *= sclo;
            oAcc[n][1] *= sclo;
            oAcc[n][2] *= schi;
            oAcc[n][3] *= schi;
        }

        // oAcc += P V
        #pragma unroll
        for (int s = 0; s < 4; ++s) {
            unsigned aP[4];
            aP[0] = pPk[2*s][0];
            aP[1] = pPk[2*s][1];
            aP[2] = pPk[2*s+1][0];
            aP[3] = pPk[2*s+1][1];
            #pragma unroll
            for (int pr = 0; pr < 2; ++pr) {
                unsigned bvf[4];
                unsigned rv = vsB + (((pr * 16 + brow) * VSTR + s * 16 + bcol) << 1);
                ldmx4(bvf[0], bvf[1], bvf[2], bvf[3], rv);
                mma16816(oAcc[2*pr],   aP, &bvf[0], oAcc[2*pr]);
                mma16816(oAcc[2*pr+1], aP, &bvf[2], oAcc[2*pr+1]);
            }
        }

        if (kc < 15) {
            CP_WAIT0();
            __syncthreads();
        }
    }

    // quad-reduce the lane-local l partials (once)
    l_lo += __shfl_xor_sync(0xffffffffu, l_lo, 1);
    l_lo += __shfl_xor_sync(0xffffffffu, l_lo, 2);
    l_hi += __shfl_xor_sync(0xffffffffu, l_hi, 1);
    l_hi += __shfl_xor_sync(0xffffffffu, l_hi, 2);

    // epilogue: normalize, stage as half (Ysm = Qsm alias; per-warp rows)
    {
        float ilo = 1.0f / l_lo;
        float ihi = 1.0f / l_hi;
        int rlo = warp * 16 + (lane >> 2);
        int cb  = (lane & 3) * 2;
        #pragma unroll
        for (int n = 0; n < 4; ++n) {
            int c = n * 8 + cb;
            *(__half2*)&Ysm[rlo * QSTR + c] =
                __floats2half2_rn(oAcc[n][0] * ilo, oAcc[n][1] * ilo);
            *(__half2*)&Ysm[(rlo + 8) * QSTR + c] =
                __floats2half2_rn(oAcc[n][2] * ihi, oAcc[n][3] * ihi);
        }
    }
    __syncthreads();
    {
        #pragma unroll
        for (int i = 0; i < 2; ++i) {
            int idx = t + i * 256;
            int row = idx >> 2;
            int seg = idx & 3;
            *(uint4*)(Yh + ((size_t)b * HW + q0 + row) * CM + seg * 8) =
                *(uint4*)&Ysm[row * QSTR + seg * 8];
        }
    }
}

// ---------------------------------------------------------------------------
// Kernel 3: z = conv1x1(y, w_W) + b_W + x via tensor cores.
// grid (32 px-tiles of 128, B), 256 threads = 8 warps (16 px each).
// ---------------------------------------------------------------------------
#define OUT_YSM  0
#define OUT_WSM  10240
#define OUT_BSD  15360
#define OUT_OSM  15616
#define OSTR     132
#define SMEM3_BYTES (15616 + 64 * OSTR * 4)

__global__ void __launch_bounds__(256) out_kernel(
    const float* __restrict__ xg, const float* __restrict__ w_W,
    const float* __restrict__ b_W, float* __restrict__ outg)
{
    extern __shared__ char osraw[];
    __half* ysm = (__half*)(osraw + OUT_YSM);   // [128 px][QSTR]
    __half* wsm = (__half*)(osraw + OUT_WSM);   // [64 out][QSTR]
    float*  bsd = (float*)(osraw + OUT_BSD);    // [64]
    float*  osm = (float*)(osraw + OUT_OSM);    // [64 out][OSTR px]

    const int t    = threadIdx.x;
    const int warp = t >> 5;
    const int lane = t & 31;
    const int tile = blockIdx.x;
    const int b    = blockIdx.y;

    // load y tile (half): 128 rows x 32 halfs = 512 uint4
    {
        #pragma unroll
        for (int i = 0; i < 2; ++i) {
            int idx = t + i * 256;
            int row = idx >> 2;
            int seg = idx & 3;
            *(uint4*)&ysm[row * QSTR + seg * 8] =
                *(const uint4*)(Yh + ((size_t)b * HW + tile * 128 + row) * CM + seg * 8);
        }
    }
    // weights -> half
    for (int i = t; i < 2048; i += 256) {
        wsm[(i >> 5) * QSTR + (i & 31)] = __float2half(w_W[i]);
    }
    if (t < 64) {
        bsd[t] = b_W[t];
    }
    __syncthreads();

    // A fragments (y): 16 px rows per warp, k=32 -> 2 k-steps
    unsigned aY0[4];
    unsigned aY1[4];
    {
        int arow = lane & 15;
        int acol = (lane >> 4) << 3;
        unsigned base = smem_u32(ysm);
        unsigned ad = base + (((warp * 16 + arow) * QSTR + acol) << 1);
        ldmx4(aY0[0], aY0[1], aY0[2], aY0[3], ad);
        ldmx4(aY1[0], aY1[1], aY1[2], aY1[3], ad + 32);
    }

    const int brow = ((lane >> 4) << 3) + (lane & 7);
    const int bcol = ((lane >> 3) & 1) << 3;
    const unsigned wBase = smem_u32(wsm);

    float cf[8][4];
    #pragma unroll
    for (int nt = 0; nt < 8; ++nt) {
        cf[nt][0] = 0.f; cf[nt][1] = 0.f; cf[nt][2] = 0.f; cf[nt][3] = 0.f;
    }
    #pragma unroll
    for (int g = 0; g < 4; ++g) {
        unsigned bw[4];
        unsigned ra = wBase + (((g * 16 + brow) * QSTR + bcol) << 1);
        ldmx4(bw[0], bw[1], bw[2], bw[3], ra);
        mma16816(cf[2*g],   aY0, &bw[0], cf[2*g]);
        mma16816(cf[2*g+1], aY0, &bw[2], cf[2*g+1]);
        ldmx4(bw[0], bw[1], bw[2], bw[3], ra + 32);
        mma16816(cf[2*g],   aY1, &bw[0], cf[2*g]);
        mma16816(cf[2*g+1], aY1, &bw[2], cf[2*g+1]);
    }

    // stage to osm[out][px] with bias
    {
        int rlo = warp * 16 + (lane >> 2);
        int cb  = (lane & 3) * 2;
        #pragma unroll
        for (int nt = 0; nt < 8; ++nt) {
            int c = nt * 8 + cb;
            float bc0 = bsd[c];
            float bc1 = bsd[c + 1];
            osm[c * OSTR + rlo]           = cf[nt][0] + bc0;
            osm[(c + 1) * OSTR + rlo]     = cf[nt][1] + bc1;
            osm[c * OSTR + rlo + 8]       = cf[nt][2] + bc0;
            osm[(c + 1) * OSTR + rlo + 8] = cf[nt][3] + bc1;
        }
    }
    __syncthreads();

    // residual add + store: 128 px x 64 out = 2048 float4
    {
        #pragma unroll
        for (int i = 0; i < 8; ++i) {
            int idx = t + i * 256;
            int co = idx >> 5;
            int p4 = idx & 31;
            float4 yv = *(const float4*)&osm[co * OSTR + p4 * 4];
            size_t gi = ((size_t)b * CI + co) * HW + tile * 128 + p4 * 4;
            float4 xv = *(const float4*)&xg[gi];
            float4 ov;
            ov.x = yv.x + xv.x;
            ov.y = yv.y + xv.y;
            ov.z = yv.z + xv.z;
            ov.w = yv.w + xv.w;
            *(float4*)&outg[gi] = ov;
        }
    }
}

// ---------------------------------------------------------------------------
extern "C" void kernel_launch(void* const* d_in, const int* in_sizes, int n_in,
                              void* d_out, int out_size)
{
    const float* xg   = (const float*)d_in[0];
    const float* w_or = (const float*)d_in[1];
    const float* b_or = (const float*)d_in[2];
    const float* w_th = (const float*)d_in[3];
    const float* b_th = (const float*)d_in[4];
    const float* w_ph = (const float*)d_in[5];
    const float* b_ph = (const float*)d_in[6];
    const float* w_W  = (const float*)d_in[7];
    const float* b_W  = (const float*)d_in[8];
    float* outg = (float*)d_out;

    cudaFuncSetAttribute(qkv_kernel, cudaFuncAttributeMaxDynamicSharedMemorySize,
                         SMEM1_BYTES);
    cudaFuncSetAttribute(out_kernel, cudaFuncAttributeMaxDynamicSharedMemorySize,
                         SMEM3_BYTES);

    qkv_kernel<<<dim3(32, NB), 128, SMEM1_BYTES>>>(xg, w_or, b_or, w_th, b_th,
                                                   w_ph, b_ph);
    attn_kernel<<<dim3(32, NB), 256>>>();
    out_kernel<<<dim3(32, NB), 256, SMEM3_BYTES>>>(xg, w_W, b_W, outg);
}

// round 8
// speedup vs baseline: 11.7997x; 1.0337x over previous
#include <cuda_runtime.h>
#include <cuda_fp16.h>

#define NB   16
#define CI   64
#define CM   32
#define HW   4096
#define NKV  1024

// Scratch (static device globals; no allocation allowed)
__device__ __half Qh[(size_t)NB * HW * CM];    // [B][4096 q][32 c]
__device__ __half Kh[(size_t)NB * NKV * CM];   // [B][1024 kv][32 c]
__device__ __half Vth[(size_t)NB * CM * NKV];  // [B][32 c][1024 kv]

// ---------------------------------------------------------------------------
// helpers
// ---------------------------------------------------------------------------
__device__ __forceinline__ unsigned smem_u32(const void* p) {
    return (unsigned)__cvta_generic_to_shared(p);
}

__device__ __forceinline__ void ldmx4(unsigned& r0, unsigned& r1, unsigned& r2,
                                      unsigned& r3, unsigned addr) {
    asm volatile("ldmatrix.sync.aligned.m8n8.x4.shared.b16 {%0,%1,%2,%3}, [%4];\n"
                 : "=r"(r0), "=r"(r1), "=r"(r2), "=r"(r3) : "r"(addr));
}

__device__ __forceinline__ void mma16816(float* dd, const unsigned* aa,
                                         const unsigned* bb, const float* cc) {
    asm volatile(
        "mma.sync.aligned.m16n8k16.row.col.f32.f16.f16.f32 "
        "{%0,%1,%2,%3},{%4,%5,%6,%7},{%8,%9},{%10,%11,%12,%13};\n"
        : "=f"(dd[0]), "=f"(dd[1]), "=f"(dd[2]), "=f"(dd[3])
        : "r"(aa[0]), "r"(aa[1]), "r"(aa[2]), "r"(aa[3]),
          "r"(bb[0]), "r"(bb[1]),
          "f"(cc[0]), "f"(cc[1]), "f"(cc[2]), "f"(cc[3]));
}

__device__ __forceinline__ unsigned packh2(float av, float bv) {
    __half2 hh = __floats2half2_rn(av, bv);
    return *(unsigned*)&hh;
}

__device__ __forceinline__ unsigned ex2h2(unsigned in) {
    unsigned r;
    asm("ex2.approx.f16x2 %0, %1;\n" : "=r"(r) : "r"(in));
    return r;
}

#define CP_ASYNC16(sa, g) \
    asm volatile("cp.async.cg.shared.global [%0], [%1], 16;\n" :: "r"(sa), "l"(g))
#define CP_COMMIT() asm volatile("cp.async.commit_group;\n")
#define CP_WAIT0()  asm volatile("cp.async.wait_group 0;\n" ::: "memory")

#define L2E 1.4426950408889634f

// ---------------------------------------------------------------------------
// Kernel 1: qkv via tensor cores. 256 threads = 8 warps (16-px strip each).
// grid (32 row-pairs, B).
// ---------------------------------------------------------------------------
#define XSTR 72
#define WSTR 72
#define QKV_XSH   0
#define QKV_WSH   18432
#define QKV_BIAS  32256
#define SMEM1_BYTES (32256 + 384)

__global__ void __launch_bounds__(256) qkv_kernel(
    const float* __restrict__ xg,
    const float* __restrict__ w_or, const float* __restrict__ b_or,
    const float* __restrict__ w_th, const float* __restrict__ b_th,
    const float* __restrict__ w_ph, const float* __restrict__ b_ph)
{
    extern __shared__ char smraw[];
    __half* xsh  = (__half*)(smraw + QKV_XSH);    // [128 px][XSTR]
    __half* wsh  = (__half*)(smraw + QKV_WSH);    // [96 out][WSTR]
    float*  bias = (float*)(smraw + QKV_BIAS);    // [96]
    float*  stg  = (float*)(smraw + QKV_XSH);     // alias: [128 px][33] fp32

    const int t    = threadIdx.x;
    const int warp = t >> 5;
    const int lane = t & 31;
    const int hp   = blockIdx.x;
    const int b    = blockIdx.y;

    // weights -> wsh (half): rows 0-31 theta, 32-63 phi, 64-95 origin
    for (int i = t; i < 2048; i += 256) {
        int r = i >> 6;
        int c = i & 63;
        wsh[r * WSTR + c]        = __float2half(w_th[i]);
        wsh[(32 + r) * WSTR + c] = __float2half(w_ph[i]);
        wsh[(64 + r) * WSTR + c] = __float2half(w_or[i]);
    }
    if (t < 32) {
        bias[t]      = b_th[t];
        bias[32 + t] = b_ph[t];
        bias[64 + t] = b_or[t];
    }

    // x tile: each thread loads 4 px x 8 ch as float4, packs, STS uint4
    {
        const int p0 = (t & 31) * 4;
        const int c0 = (t >> 5) * 8;
        const float* xb = xg + ((size_t)b * CI + c0) * HW + hp * 128 + p0;
        unsigned wbuf[4][4];
        #pragma unroll
        for (int cc = 0; cc < 4; ++cc) {
            float4 va = *(const float4*)(xb + (size_t)(2 * cc) * HW);
            float4 vb = *(const float4*)(xb + (size_t)(2 * cc + 1) * HW);
            wbuf[0][cc] = packh2(va.x, vb.x);
            wbuf[1][cc] = packh2(va.y, vb.y);
            wbuf[2][cc] = packh2(va.z, vb.z);
            wbuf[3][cc] = packh2(va.w, vb.w);
        }
        #pragma unroll
        for (int j = 0; j < 4; ++j) {
            uint4 u0;
            u0.x = wbuf[j][0]; u0.y = wbuf[j][1]; u0.z = wbuf[j][2]; u0.w = wbuf[j][3];
            *(uint4*)&xsh[(p0 + j) * XSTR + c0] = u0;
        }
    }
    __syncthreads();

    // A fragments: warp px strip [warp*16, warp*16+15], 4 k-steps
    unsigned aX[4][4];
    {
        int arow = lane & 15;
        int acol = (lane >> 4) << 3;
        unsigned base = smem_u32(xsh);
        #pragma unroll
        for (int k = 0; k < 4; ++k) {
            unsigned ad = base +
                (((warp * 16 + arow) * XSTR + k * 16 + acol) << 1);
            ldmx4(aX[k][0], aX[k][1], aX[k][2], aX[k][3], ad);
        }
    }
    __syncthreads();   // xsh is now dead; stg may overwrite it

    const int brow = ((lane >> 4) << 3) + (lane & 7);
    const int bcol = ((lane >> 3) & 1) << 3;
    const unsigned wshBase = smem_u32(wsh);

    #pragma unroll 1
    for (int g = 0; g < 3; ++g) {
        float cf[4][4];
        #pragma unroll
        for (int nt = 0; nt < 4; ++nt) {
            cf[nt][0] = 0.f; cf[nt][1] = 0.f; cf[nt][2] = 0.f; cf[nt][3] = 0.f;
        }
        #pragma unroll
        for (int nt2 = 0; nt2 < 2; ++nt2) {
            #pragma unroll
            for (int k = 0; k < 4; ++k) {
                unsigned bw[4];
                unsigned ra = wshBase +
                    (((g * 32 + nt2 * 16 + brow) * WSTR + k * 16 + bcol) << 1);
                ldmx4(bw[0], bw[1], bw[2], bw[3], ra);
                mma16816(cf[nt2*2],   aX[k], &bw[0], cf[nt2*2]);
                mma16816(cf[nt2*2+1], aX[k], &bw[2], cf[nt2*2+1]);
            }
        }
        // add bias
        #pragma unroll
        for (int nt = 0; nt < 4; ++nt) {
            int o0 = g * 32 + nt * 8 + (lane & 3) * 2;
            cf[nt][0] += bias[o0];
            cf[nt][1] += bias[o0 + 1];
            cf[nt][2] += bias[o0];
            cf[nt][3] += bias[o0 + 1];
        }

        if (g == 0) {
            __half2* Qb = (__half2*)(Qh + ((size_t)b * HW + hp * 128) * CM);
            int row = warp * 16 + (lane >> 2);
            #pragma unroll
            for (int nt = 0; nt < 4; ++nt) {
                int cp = (nt * 8 + (lane & 3) * 2) >> 1;
                Qb[row * 16 + cp]       = __floats2half2_rn(cf[nt][0], cf[nt][1]);
                Qb[(row + 8) * 16 + cp] = __floats2half2_rn(cf[nt][2], cf[nt][3]);
            }
        } else {
            int row = warp * 16 + (lane >> 2);
            #pragma unroll
            for (int nt = 0; nt < 4; ++nt) {
                int c0 = nt * 8 + (lane & 3) * 2;
                stg[row * 33 + c0]           = cf[nt][0];
                stg[row * 33 + c0 + 1]       = cf[nt][1];
                stg[(row + 8) * 33 + c0]     = cf[nt][2];
                stg[(row + 8) * 33 + c0 + 1] = cf[nt][3];
            }
            __syncthreads();
            if (g == 1) {
                #pragma unroll
                for (int i = 0; i < 4; ++i) {
                    int idx = t + i * 256;
                    int kw = idx >> 5;
                    int o  = idx & 31;
                    float mv = fmaxf(
                        fmaxf(stg[(2*kw) * 33 + o], stg[(2*kw + 1) * 33 + o]),
                        fmaxf(stg[(64 + 2*kw) * 33 + o], stg[(65 + 2*kw) * 33 + o]));
                    Kh[((size_t)b * NKV + hp * 32 + kw) * CM + o] = __float2half(mv);
                }
            } else {
                #pragma unroll
                for (int i = 0; i < 4; ++i) {
                    int idx = t + i * 256;
                    int o  = idx >> 5;
                    int kw = idx & 31;
                    float mv = fmaxf(
                        fmaxf(stg[(2*kw) * 33 + o], stg[(2*kw + 1) * 33 + o]),
                        fmaxf(stg[(64 + 2*kw) * 33 + o], stg[(65 + 2*kw) * 33 + o]));
                    Vth[((size_t)b * CM + o) * NKV + hp * 32 + kw] = __float2half(mv);
                }
            }
            __syncthreads();
        }
    }
}

// ---------------------------------------------------------------------------
// Kernel 2: FUSED attention + output conv + residual.
// grid (32 q-tiles of 128, B), 256 threads = 8 warps.
// After online-softmax attention, the same block computes
// out = Y * w_W^T + b_W + x for its 128-px tile (no Yh round-trip).
// Smem: osm (fp32 staging) aliases the dead Ksm/Vsm buffers.
// ---------------------------------------------------------------------------
#define QSTR 40
#define VSTR 72
#define OSTR 132
#define AT_QSM  0
#define AT_WSM  10240
#define AT_BSD  15360
#define AT_KSM  15616
#define AT_VSM  25856
#define AT_OSM  15616              // alias over Ksm+Vsm (dead after mainloop)
#define SMEM2_BYTES (15616 + 64 * OSTR * 4)   // 49408

__global__ void __launch_bounds__(256) attn_kernel(
    const float* __restrict__ xg, const float* __restrict__ w_W,
    const float* __restrict__ b_W, float* __restrict__ outg)
{
    extern __shared__ char atraw[];
    __half* Qsm = (__half*)(atraw + AT_QSM);   // [128 q][QSTR]; Ysm in epilogue
    __half* wsm = (__half*)(atraw + AT_WSM);   // [64 out][QSTR]
    float*  bsd = (float*)(atraw + AT_BSD);    // [64]
    __half* Ksm = (__half*)(atraw + AT_KSM);   // 2 x [64 kv][QSTR]
    __half* Vsm = (__half*)(atraw + AT_VSM);   // 2 x [32 c][VSTR]
    float*  osm = (float*)(atraw + AT_OSM);    // [64 out][OSTR] (alias)
    __half* Ysm = Qsm;

    const int t    = threadIdx.x;
    const int warp = t >> 5;
    const int lane = t & 31;
    const int b    = blockIdx.y;
    const int q0   = blockIdx.x * 128;

    // prologue: Q tile + chunk 0 of K/V via cp.async; w_W/b_W via plain loads
    {
        #pragma unroll
        for (int i = 0; i < 2; ++i) {
            int idx = t + i * 256;
            int row = idx >> 2;
            int seg = idx & 3;
            CP_ASYNC16(smem_u32(&Qsm[row * QSTR + seg * 8]),
                       Qh + ((size_t)b * HW + q0 + row) * CM + seg * 8);
        }
        {
            int row = t >> 2;
            int seg = t & 3;
            CP_ASYNC16(smem_u32(&Ksm[row * QSTR + seg * 8]),
                       Kh + ((size_t)b * NKV + row) * CM + seg * 8);
        }
        {
            int row = t >> 3;
            int seg = t & 7;
            CP_ASYNC16(smem_u32(&Vsm[row * VSTR + seg * 8]),
                       Vth + ((size_t)b * CM + row) * NKV + seg * 8);
        }
        for (int i = t; i < 2048; i += 256) {
            wsm[(i >> 5) * QSTR + (i & 31)] = __float2half(w_W[i]);
        }
        if (t < 64) {
            bsd[t] = b_W[t];
        }
        CP_COMMIT();
        CP_WAIT0();
        __syncthreads();
    }

    // A-operand (Q) fragments for 2 k-steps
    unsigned aQ0[4];
    unsigned aQ1[4];
    {
        int arow = lane & 15;
        int acol = (lane >> 4) << 3;
        unsigned base = smem_u32(Qsm);
        unsigned ad0 = base + (((warp * 16 + arow) * QSTR + acol) << 1);
        ldmx4(aQ0[0], aQ0[1], aQ0[2], aQ0[3], ad0);
        ldmx4(aQ1[0], aQ1[1], aQ1[2], aQ1[3], ad0 + 32);
    }

    const int brow = ((lane >> 4) << 3) + (lane & 7);
    const int bcol = ((lane >> 3) & 1) << 3;
    const unsigned ksBase = smem_u32(Ksm);
    const unsigned vsBase = smem_u32(Vsm);

    float oAcc[4][4];
    #pragma unroll
    for (int n = 0; n < 4; ++n) {
        oAcc[n][0] = 0.f; oAcc[n][1] = 0.f; oAcc[n][2] = 0.f; oAcc[n][3] = 0.f;
    }
    float m_lo = -1e30f;
    float m_hi = -1e30f;
    float l_lo = 0.f;   // lane-local partial; quad-reduced after the loop
    float l_hi = 0.f;

    for (int kc = 0; kc < 16; ++kc) {
        const int cur = kc & 1;
        if (kc < 15) {
            int nxt = cur ^ 1;
            {
                int row = t >> 2;
                int seg = t & 3;
                CP_ASYNC16(smem_u32(&Ksm[nxt * 64 * QSTR + row * QSTR + seg * 8]),
                           Kh + ((size_t)b * NKV + (kc + 1) * 64 + row) * CM + seg * 8);
            }
            {
                int row = t >> 3;
                int seg = t & 7;
                CP_ASYNC16(smem_u32(&Vsm[nxt * 32 * VSTR + row * VSTR + seg * 8]),
                           Vth + ((size_t)b * CM + row) * NKV + (kc + 1) * 64 + seg * 8);
            }
            CP_COMMIT();
        }
        const unsigned ksB = ksBase + cur * (64 * QSTR * 2);
        const unsigned vsB = vsBase + cur * (32 * VSTR * 2);

        // sAcc = Q K^T for this 64-kv chunk
        float sAcc[8][4];
        #pragma unroll
        for (int j = 0; j < 8; ++j) {
            sAcc[j][0] = 0.f; sAcc[j][1] = 0.f; sAcc[j][2] = 0.f; sAcc[j][3] = 0.f;
        }
        #pragma unroll
        for (int g = 0; g < 4; ++g) {
            unsigned bkf[4];
            unsigned ra = ksB + (((g * 16 + brow) * QSTR + bcol) << 1);
            ldmx4(bkf[0], bkf[1], bkf[2], bkf[3], ra);
            mma16816(sAcc[2*g],   aQ0, &bkf[0], sAcc[2*g]);
            mma16816(sAcc[2*g+1], aQ0, &bkf[2], sAcc[2*g+1]);
            ldmx4(bkf[0], bkf[1], bkf[2], bkf[3], ra + 32);
            mma16816(sAcc[2*g],   aQ1, &bkf[0], sAcc[2*g]);
            mma16816(sAcc[2*g+1], aQ1, &bkf[2], sAcc[2*g+1]);
        }

        // online softmax: packed half2 max reduce (2 shuffles)
        float mlo = -1e30f;
        float mhi = -1e30f;
        #pragma unroll
        for (int j = 0; j < 8; ++j) {
            mlo = fmaxf(mlo, fmaxf(sAcc[j][0], sAcc[j][1]));
            mhi = fmaxf(mhi, fmaxf(sAcc[j][2], sAcc[j][3]));
        }
        {
            unsigned mp = packh2(mlo, mhi);
            __half2 mh = *(__half2*)&mp;
            unsigned ms1 = __shfl_xor_sync(0xffffffffu, mp, 1);
            mh = __hmax2(mh, *(__half2*)&ms1);
            unsigned mhu = *(unsigned*)&mh;
            unsigned ms2 = __shfl_xor_sync(0xffffffffu, mhu, 2);
            mh = __hmax2(mh, *(__half2*)&ms2);
            mlo = __low2float(mh);
            mhi = __high2float(mh);
        }
        float nmlo = fmaxf(m_lo, mlo);
        float nmhi = fmaxf(m_hi, mhi);
        float sclo = __expf(m_lo - nmlo);
        float schi = __expf(m_hi - nmhi);
        m_lo = nmlo;
        m_hi = nmhi;

        // P = exp(s - m) in fp16x2 via ex2.approx.f16x2; lane-local sums
        const float mlo2 = nmlo * L2E;
        const float mhi2 = nmhi * L2E;
        float slo = 0.f;
        float shi = 0.f;
        unsigned pPk[8][2];
        #pragma unroll
        for (int j = 0; j < 8; ++j) {
            float e0 = fmaf(sAcc[j][0], L2E, -mlo2);
            float e1 = fmaf(sAcc[j][1], L2E, -mlo2);
            float e2 = fmaf(sAcc[j][2], L2E, -mhi2);
            float e3 = fmaf(sAcc[j][3], L2E, -mhi2);
            unsigned plo = ex2h2(packh2(e0, e1));
            unsigned phi = ex2h2(packh2(e2, e3));
            pPk[j][0] = plo;
            pPk[j][1] = phi;
            float2 flo = __half22float2(*(__half2*)&plo);
            float2 fhi = __half22float2(*(__half2*)&phi);
            slo += flo.x + flo.y;
            shi += fhi.x + fhi.y;
        }
        l_lo = l_lo * sclo + slo;
        l_hi = l_hi * schi + shi;
        #pragma unroll
        for (int n = 0; n < 4; ++n) {
            oAcc[n][0] *= sclo;
            oAcc[n][1] *= sclo;
            oAcc[n][2] *= schi;
            oAcc[n][3] *= schi;
        }

        // oAcc += P V
        #pragma unroll
        for (int s = 0; s < 4; ++s) {
            unsigned aP[4];
            aP[0] = pPk[2*s][0];
            aP[1] = pPk[2*s][1];
            aP[2] = pPk[2*s+1][0];
            aP[3] = pPk[2*s+1][1];
            #pragma unroll
            for (int pr = 0; pr < 2; ++pr) {
                unsigned bvf[4];
                unsigned rv = vsB + (((pr * 16 + brow) * VSTR + s * 16 + bcol) << 1);
                ldmx4(bvf[0], bvf[1], bvf[2], bvf[3], rv);
                mma16816(oAcc[2*pr],   aP, &bvf[0], oAcc[2*pr]);
                mma16816(oAcc[2*pr+1], aP, &bvf[2], oAcc[2*pr+1]);
            }
        }

        if (kc < 15) {
            CP_WAIT0();
            __syncthreads();
        }
    }

    // quad-reduce the lane-local l partials (once)
    l_lo += __shfl_xor_sync(0xffffffffu, l_lo, 1);
    l_lo += __shfl_xor_sync(0xffffffffu, l_lo, 2);
    l_hi += __shfl_xor_sync(0xffffffffu, l_hi, 1);
    l_hi += __shfl_xor_sync(0xffffffffu, l_hi, 2);

    // normalize, stage Y as half into Ysm (= Qsm alias; per-warp rows)
    {
        float ilo = 1.0f / l_lo;
        float ihi = 1.0f / l_hi;
        int rlo = warp * 16 + (lane >> 2);
        int cb  = (lane & 3) * 2;
        #pragma unroll
        for (int n = 0; n < 4; ++n) {
            int c = n * 8 + cb;
            *(__half2*)&Ysm[rlo * QSTR + c] =
                __floats2half2_rn(oAcc[n][0] * ilo, oAcc[n][1] * ilo);
            *(__half2*)&Ysm[(rlo + 8) * QSTR + c] =
                __floats2half2_rn(oAcc[n][2] * ihi, oAcc[n][3] * ihi);
        }
    }
    __syncthreads();   // Ysm complete; Ksm/Vsm dead -> osm may overwrite

    // ---- fused output conv: out = Y * w_W^T + b_W + x ----
    unsigned aY0[4];
    unsigned aY1[4];
    {
        int arow = lane & 15;
        int acol = (lane >> 4) << 3;
        unsigned base = smem_u32(Ysm);
        unsigned ad = base + (((warp * 16 + arow) * QSTR + acol) << 1);
        ldmx4(aY0[0], aY0[1], aY0[2], aY0[3], ad);
        ldmx4(aY1[0], aY1[1], aY1[2], aY1[3], ad + 32);
    }

    const unsigned wBase = smem_u32(wsm);
    float cf[8][4];
    #pragma unroll
    for (int nt = 0; nt < 8; ++nt) {
        cf[nt][0] = 0.f; cf[nt][1] = 0.f; cf[nt][2] = 0.f; cf[nt][3] = 0.f;
    }
    #pragma unroll
    for (int g = 0; g < 4; ++g) {
        unsigned bw[4];
        unsigned ra = wBase + (((g * 16 + brow) * QSTR + bcol) << 1);
        ldmx4(bw[0], bw[1], bw[2], bw[3], ra);
        mma16816(cf[2*g],   aY0, &bw[0], cf[2*g]);
        mma16816(cf[2*g+1], aY0, &bw[2], cf[2*g+1]);
        ldmx4(bw[0], bw[1], bw[2], bw[3], ra + 32);
        mma16816(cf[2*g],   aY1, &bw[0], cf[2*g]);
        mma16816(cf[2*g+1], aY1, &bw[2], cf[2*g+1]);
    }

    // stage to osm[out][px] with bias
    {
        int rlo = warp * 16 + (lane >> 2);
        int cb  = (lane & 3) * 2;
        #pragma unroll
        for (int nt = 0; nt < 8; ++nt) {
            int c = nt * 8 + cb;
            float bc0 = bsd[c];
            float bc1 = bsd[c + 1];
            osm[c * OSTR + rlo]           = cf[nt][0] + bc0;
            osm[(c + 1) * OSTR + rlo]     = cf[nt][1] + bc1;
            osm[c * OSTR + rlo + 8]       = cf[nt][2] + bc0;
            osm[(c + 1) * OSTR + rlo + 8] = cf[nt][3] + bc1;
        }
    }
    __syncthreads();

    // residual add + store: 128 px x 64 out = 2048 float4
    {
        #pragma unroll
        for (int i = 0; i < 8; ++i) {
            int idx = t + i * 256;
            int co = idx >> 5;
            int p4 = idx & 31;
            float4 yv = *(const float4*)&osm[co * OSTR + p4 * 4];
            size_t gi = ((size_t)b * CI + co) * HW + q0 + p4 * 4;
            float4 xv = *(const float4*)&xg[gi];
            float4 ov;
            ov.x = yv.x + xv.x;
            ov.y = yv.y + xv.y;
            ov.z = yv.z + xv.z;
            ov.w = yv.w + xv.w;
            *(float4*)&outg[gi] = ov;
        }
    }
}

// ---------------------------------------------------------------------------
extern "C" void kernel_launch(void* const* d_in, const int* in_sizes, int n_in,
                              void* d_out, int out_size)
{
    const float* xg   = (const float*)d_in[0];
    const float* w_or = (const float*)d_in[1];
    const float* b_or = (const float*)d_in[2];
    const float* w_th = (const float*)d_in[3];
    const float* b_th = (const float*)d_in[4];
    const float* w_ph = (const float*)d_in[5];
    const float* b_ph = (const float*)d_in[6];
    const float* w_W  = (const float*)d_in[7];
    const float* b_W  = (const float*)d_in[8];
    float* outg = (float*)d_out;

    cudaFuncSetAttribute(qkv_kernel, cudaFuncAttributeMaxDynamicSharedMemorySize,
                         SMEM1_BYTES);
    cudaFuncSetAttribute(attn_kernel, cudaFuncAttributeMaxDynamicSharedMemorySize,
                         SMEM2_BYTES);

    qkv_kernel<<<dim3(32, NB), 256, SMEM1_BYTES>>>(xg, w_or, b_or, w_th, b_th,
                                                   w_ph, b_ph);
    attn_kernel<<<dim3(32, NB), 256, SMEM2_BYTES>>>(xg, w_W, b_W, outg);
}

// round 9
// speedup vs baseline: 12.0903x; 1.0246x over previous
#include <cuda_runtime.h>
#include <cuda_fp16.h>

#define NB   16
#define CI   64
#define CM   32
#define HW   4096
#define NKV  1024

// Scratch (static device globals; no allocation allowed)
__device__ __half Qh[(size_t)NB * HW * CM];    // [B][4096 q][32 c]
__device__ __half Kh[(size_t)NB * NKV * CM];   // [B][1024 kv][32 c]
__device__ __half Vth[(size_t)NB * CM * NKV];  // [B][32 c][1024 kv]

// ---------------------------------------------------------------------------
// helpers
// ---------------------------------------------------------------------------
__device__ __forceinline__ unsigned smem_u32(const void* p) {
    return (unsigned)__cvta_generic_to_shared(p);
}

__device__ __forceinline__ void ldmx4(unsigned& r0, unsigned& r1, unsigned& r2,
                                      unsigned& r3, unsigned addr) {
    asm volatile("ldmatrix.sync.aligned.m8n8.x4.shared.b16 {%0,%1,%2,%3}, [%4];\n"
                 : "=r"(r0), "=r"(r1), "=r"(r2), "=r"(r3) : "r"(addr));
}

__device__ __forceinline__ void mma16816(float* dd, const unsigned* aa,
                                         const unsigned* bb, const float* cc) {
    asm volatile(
        "mma.sync.aligned.m16n8k16.row.col.f32.f16.f16.f32 "
        "{%0,%1,%2,%3},{%4,%5,%6,%7},{%8,%9},{%10,%11,%12,%13};\n"
        : "=f"(dd[0]), "=f"(dd[1]), "=f"(dd[2]), "=f"(dd[3])
        : "r"(aa[0]), "r"(aa[1]), "r"(aa[2]), "r"(aa[3]),
          "r"(bb[0]), "r"(bb[1]),
          "f"(cc[0]), "f"(cc[1]), "f"(cc[2]), "f"(cc[3]));
}

__device__ __forceinline__ unsigned packh2(float av, float bv) {
    __half2 hh = __floats2half2_rn(av, bv);
    return *(unsigned*)&hh;
}

__device__ __forceinline__ unsigned ex2h2(unsigned in) {
    unsigned r;
    asm("ex2.approx.f16x2 %0, %1;\n" : "=r"(r) : "r"(in));
    return r;
}

#define CP_ASYNC16(sa, g) \
    asm volatile("cp.async.cg.shared.global [%0], [%1], 16;\n" :: "r"(sa), "l"(g))
#define CP_COMMIT() asm volatile("cp.async.commit_group;\n")
#define CP_WAIT0()  asm volatile("cp.async.wait_group 0;\n" ::: "memory")

#define L2E 1.4426950408889634f

// ---------------------------------------------------------------------------
// Kernel 1: qkv via tensor cores. 256 threads = 8 warps (16-px strip each).
// grid (32 row-pairs, B).
// ---------------------------------------------------------------------------
#define XSTR 72
#define WSTR 72
#define QKV_XSH   0
#define QKV_WSH   18432
#define QKV_BIAS  32256
#define SMEM1_BYTES (32256 + 384)

__global__ void __launch_bounds__(256, 3) qkv_kernel(
    const float* __restrict__ xg,
    const float* __restrict__ w_or, const float* __restrict__ b_or,
    const float* __restrict__ w_th, const float* __restrict__ b_th,
    const float* __restrict__ w_ph, const float* __restrict__ b_ph)
{
    extern __shared__ char smraw[];
    __half* xsh  = (__half*)(smraw + QKV_XSH);    // [128 px][XSTR]
    __half* wsh  = (__half*)(smraw + QKV_WSH);    // [96 out][WSTR]
    float*  bias = (float*)(smraw + QKV_BIAS);    // [96]
    float*  stg  = (float*)(smraw + QKV_XSH);     // alias: [128 px][33] fp32

    const int t    = threadIdx.x;
    const int warp = t >> 5;
    const int lane = t & 31;
    const int hp   = blockIdx.x;
    const int b    = blockIdx.y;

    // weights -> wsh (half): rows 0-31 theta, 32-63 phi, 64-95 origin
    for (int i = t; i < 2048; i += 256) {
        int r = i >> 6;
        int c = i & 63;
        wsh[r * WSTR + c]        = __float2half(w_th[i]);
        wsh[(32 + r) * WSTR + c] = __float2half(w_ph[i]);
        wsh[(64 + r) * WSTR + c] = __float2half(w_or[i]);
    }
    if (t < 32) {
        bias[t]      = b_th[t];
        bias[32 + t] = b_ph[t];
        bias[64 + t] = b_or[t];
    }

    // x tile: each thread loads 4 px x 8 ch as float4, packs, STS uint4
    {
        const int p0 = (t & 31) * 4;
        const int c0 = (t >> 5) * 8;
        const float* xb = xg + ((size_t)b * CI + c0) * HW + hp * 128 + p0;
        unsigned wbuf[4][4];
        #pragma unroll
        for (int cc = 0; cc < 4; ++cc) {
            float4 va = *(const float4*)(xb + (size_t)(2 * cc) * HW);
            float4 vb = *(const float4*)(xb + (size_t)(2 * cc + 1) * HW);
            wbuf[0][cc] = packh2(va.x, vb.x);
            wbuf[1][cc] = packh2(va.y, vb.y);
            wbuf[2][cc] = packh2(va.z, vb.z);
            wbuf[3][cc] = packh2(va.w, vb.w);
        }
        #pragma unroll
        for (int j = 0; j < 4; ++j) {
            uint4 u0;
            u0.x = wbuf[j][0]; u0.y = wbuf[j][1]; u0.z = wbuf[j][2]; u0.w = wbuf[j][3];
            *(uint4*)&xsh[(p0 + j) * XSTR + c0] = u0;
        }
    }
    __syncthreads();

    // A fragments: warp px strip [warp*16, warp*16+15], 4 k-steps
    unsigned aX[4][4];
    {
        int arow = lane & 15;
        int acol = (lane >> 4) << 3;
        unsigned base = smem_u32(xsh);
        #pragma unroll
        for (int k = 0; k < 4; ++k) {
            unsigned ad = base +
                (((warp * 16 + arow) * XSTR + k * 16 + acol) << 1);
            ldmx4(aX[k][0], aX[k][1], aX[k][2], aX[k][3], ad);
        }
    }
    __syncthreads();   // xsh is now dead; stg may overwrite it

    const int brow = ((lane >> 4) << 3) + (lane & 7);
    const int bcol = ((lane >> 3) & 1) << 3;
    const unsigned wshBase = smem_u32(wsh);

    #pragma unroll 1
    for (int g = 0; g < 3; ++g) {
        float cf[4][4];
        #pragma unroll
        for (int nt = 0; nt < 4; ++nt) {
            cf[nt][0] = 0.f; cf[nt][1] = 0.f; cf[nt][2] = 0.f; cf[nt][3] = 0.f;
        }
        #pragma unroll
        for (int nt2 = 0; nt2 < 2; ++nt2) {
            #pragma unroll
            for (int k = 0; k < 4; ++k) {
                unsigned bw[4];
                unsigned ra = wshBase +
                    (((g * 32 + nt2 * 16 + brow) * WSTR + k * 16 + bcol) << 1);
                ldmx4(bw[0], bw[1], bw[2], bw[3], ra);
                mma16816(cf[nt2*2],   aX[k], &bw[0], cf[nt2*2]);
                mma16816(cf[nt2*2+1], aX[k], &bw[2], cf[nt2*2+1]);
            }
        }
        // add bias
        #pragma unroll
        for (int nt = 0; nt < 4; ++nt) {
            int o0 = g * 32 + nt * 8 + (lane & 3) * 2;
            cf[nt][0] += bias[o0];
            cf[nt][1] += bias[o0 + 1];
            cf[nt][2] += bias[o0];
            cf[nt][3] += bias[o0 + 1];
        }

        if (g == 0) {
            __half2* Qb = (__half2*)(Qh + ((size_t)b * HW + hp * 128) * CM);
            int row = warp * 16 + (lane >> 2);
            #pragma unroll
            for (int nt = 0; nt < 4; ++nt) {
                int cp = (nt * 8 + (lane & 3) * 2) >> 1;
                Qb[row * 16 + cp]       = __floats2half2_rn(cf[nt][0], cf[nt][1]);
                Qb[(row + 8) * 16 + cp] = __floats2half2_rn(cf[nt][2], cf[nt][3]);
            }
        } else {
            int row = warp * 16 + (lane >> 2);
            #pragma unroll
            for (int nt = 0; nt < 4; ++nt) {
                int c0 = nt * 8 + (lane & 3) * 2;
                stg[row * 33 + c0]           = cf[nt][0];
                stg[row * 33 + c0 + 1]       = cf[nt][1];
                stg[(row + 8) * 33 + c0]     = cf[nt][2];
                stg[(row + 8) * 33 + c0 + 1] = cf[nt][3];
            }
            __syncthreads();
            if (g == 1) {
                #pragma unroll
                for (int i = 0; i < 4; ++i) {
                    int idx = t + i * 256;
                    int kw = idx >> 5;
                    int o  = idx & 31;
                    float mv = fmaxf(
                        fmaxf(stg[(2*kw) * 33 + o], stg[(2*kw + 1) * 33 + o]),
                        fmaxf(stg[(64 + 2*kw) * 33 + o], stg[(65 + 2*kw) * 33 + o]));
                    Kh[((size_t)b * NKV + hp * 32 + kw) * CM + o] = __float2half(mv);
                }
            } else {
                #pragma unroll
                for (int i = 0; i < 4; ++i) {
                    int idx = t + i * 256;
                    int o  = idx >> 5;
                    int kw = idx & 31;
                    float mv = fmaxf(
                        fmaxf(stg[(2*kw) * 33 + o], stg[(2*kw + 1) * 33 + o]),
                        fmaxf(stg[(64 + 2*kw) * 33 + o], stg[(65 + 2*kw) * 33 + o]));
                    Vth[((size_t)b * CM + o) * NKV + hp * 32 + kw] = __float2half(mv);
                }
            }
            __syncthreads();
        }
    }
}

// ---------------------------------------------------------------------------
// Kernel 2: FUSED attention + output conv + residual.
// grid (32 q-tiles of 128, B), 256 threads = 8 warps.
// __launch_bounds__(256,3): cap regs so 3 blocks/SM stay resident.
// ---------------------------------------------------------------------------
#define QSTR 40
#define VSTR 72
#define OSTR 132
#define AT_QSM  0
#define AT_WSM  10240
#define AT_BSD  15360
#define AT_KSM  15616
#define AT_VSM  25856
#define AT_OSM  15616              // alias over Ksm+Vsm (dead after mainloop)
#define SMEM2_BYTES (15616 + 64 * OSTR * 4)   // 49408

__global__ void __launch_bounds__(256, 3) attn_kernel(
    const float* __restrict__ xg, const float* __restrict__ w_W,
    const float* __restrict__ b_W, float* __restrict__ outg)
{
    extern __shared__ char atraw[];
    __half* Qsm = (__half*)(atraw + AT_QSM);   // [128 q][QSTR]; Ysm in epilogue
    __half* wsm = (__half*)(atraw + AT_WSM);   // [64 out][QSTR]
    float*  bsd = (float*)(atraw + AT_BSD);    // [64]
    __half* Ksm = (__half*)(atraw + AT_KSM);   // 2 x [64 kv][QSTR]
    __half* Vsm = (__half*)(atraw + AT_VSM);   // 2 x [32 c][VSTR]
    float*  osm = (float*)(atraw + AT_OSM);    // [64 out][OSTR] (alias)
    __half* Ysm = Qsm;

    const int t    = threadIdx.x;
    const int warp = t >> 5;
    const int lane = t & 31;
    const int b    = blockIdx.y;
    const int q0   = blockIdx.x * 128;

    // prologue: Q tile + chunk 0 of K/V via cp.async; w_W/b_W via plain loads
    {
        #pragma unroll
        for (int i = 0; i < 2; ++i) {
            int idx = t + i * 256;
            int row = idx >> 2;
            int seg = idx & 3;
            CP_ASYNC16(smem_u32(&Qsm[row * QSTR + seg * 8]),
                       Qh + ((size_t)b * HW + q0 + row) * CM + seg * 8);
        }
        {
            int row = t >> 2;
            int seg = t & 3;
            CP_ASYNC16(smem_u32(&Ksm[row * QSTR + seg * 8]),
                       Kh + ((size_t)b * NKV + row) * CM + seg * 8);
        }
        {
            int row = t >> 3;
            int seg = t & 7;
            CP_ASYNC16(smem_u32(&Vsm[row * VSTR + seg * 8]),
                       Vth + ((size_t)b * CM + row) * NKV + seg * 8);
        }
        for (int i = t; i < 2048; i += 256) {
            wsm[(i >> 5) * QSTR + (i & 31)] = __float2half(w_W[i]);
        }
        if (t < 64) {
            bsd[t] = b_W[t];
        }
        CP_COMMIT();
        CP_WAIT0();
        __syncthreads();
    }

    // A-operand (Q) fragments for 2 k-steps
    unsigned aQ0[4];
    unsigned aQ1[4];
    {
        int arow = lane & 15;
        int acol = (lane >> 4) << 3;
        unsigned base = smem_u32(Qsm);
        unsigned ad0 = base + (((warp * 16 + arow) * QSTR + acol) << 1);
        ldmx4(aQ0[0], aQ0[1], aQ0[2], aQ0[3], ad0);
        ldmx4(aQ1[0], aQ1[1], aQ1[2], aQ1[3], ad0 + 32);
    }

    const int brow = ((lane >> 4) << 3) + (lane & 7);
    const int bcol = ((lane >> 3) & 1) << 3;
    const unsigned ksBase = smem_u32(Ksm);
    const unsigned vsBase = smem_u32(Vsm);

    float oAcc[4][4];
    #pragma unroll
    for (int n = 0; n < 4; ++n) {
        oAcc[n][0] = 0.f; oAcc[n][1] = 0.f; oAcc[n][2] = 0.f; oAcc[n][3] = 0.f;
    }
    float m_lo = -1e30f;
    float m_hi = -1e30f;
    float l_lo = 0.f;   // lane-local partial; quad-reduced after the loop
    float l_hi = 0.f;

    for (int kc = 0; kc < 16; ++kc) {
        const int cur = kc & 1;
        if (kc < 15) {
            int nxt = cur ^ 1;
            {
                int row = t >> 2;
                int seg = t & 3;
                CP_ASYNC16(smem_u32(&Ksm[nxt * 64 * QSTR + row * QSTR + seg * 8]),
                           Kh + ((size_t)b * NKV + (kc + 1) * 64 + row) * CM + seg * 8);
            }
            {
                int row = t >> 3;
                int seg = t & 7;
                CP_ASYNC16(smem_u32(&Vsm[nxt * 32 * VSTR + row * VSTR + seg * 8]),
                           Vth + ((size_t)b * CM + row) * NKV + (kc + 1) * 64 + seg * 8);
            }
            CP_COMMIT();
        }
        const unsigned ksB = ksBase + cur * (64 * QSTR * 2);
        const unsigned vsB = vsBase + cur * (32 * VSTR * 2);

        // sAcc = Q K^T for this 64-kv chunk
        float sAcc[8][4];
        #pragma unroll
        for (int j = 0; j < 8; ++j) {
            sAcc[j][0] = 0.f; sAcc[j][1] = 0.f; sAcc[j][2] = 0.f; sAcc[j][3] = 0.f;
        }
        #pragma unroll
        for (int g = 0; g < 4; ++g) {
            unsigned bkf[4];
            unsigned ra = ksB + (((g * 16 + brow) * QSTR + bcol) << 1);
            ldmx4(bkf[0], bkf[1], bkf[2], bkf[3], ra);
            mma16816(sAcc[2*g],   aQ0, &bkf[0], sAcc[2*g]);
            mma16816(sAcc[2*g+1], aQ0, &bkf[2], sAcc[2*g+1]);
            ldmx4(bkf[0], bkf[1], bkf[2], bkf[3], ra + 32);
            mma16816(sAcc[2*g],   aQ1, &bkf[0], sAcc[2*g]);
            mma16816(sAcc[2*g+1], aQ1, &bkf[2], sAcc[2*g+1]);
        }

        // online softmax: packed half2 max reduce (2 shuffles)
        float mlo = -1e30f;
        float mhi = -1e30f;
        #pragma unroll
        for (int j = 0; j < 8; ++j) {
            mlo = fmaxf(mlo, fmaxf(sAcc[j][0], sAcc[j][1]));
            mhi = fmaxf(mhi, fmaxf(sAcc[j][2], sAcc[j][3]));
        }
        {
            unsigned mp = packh2(mlo, mhi);
            __half2 mh = *(__half2*)&mp;
            unsigned ms1 = __shfl_xor_sync(0xffffffffu, mp, 1);
            mh = __hmax2(mh, *(__half2*)&ms1);
            unsigned mhu = *(unsigned*)&mh;
            unsigned ms2 = __shfl_xor_sync(0xffffffffu, mhu, 2);
            mh = __hmax2(mh, *(__half2*)&ms2);
            mlo = __low2float(mh);
            mhi = __high2float(mh);
        }
        float nmlo = fmaxf(m_lo, mlo);
        float nmhi = fmaxf(m_hi, mhi);
        float sclo = __expf(m_lo - nmlo);
        float schi = __expf(m_hi - nmhi);
        m_lo = nmlo;
        m_hi = nmhi;

        // P = exp(s - m) in fp16x2 via ex2.approx.f16x2; lane-local sums
        const float mlo2 = nmlo * L2E;
        const float mhi2 = nmhi * L2E;
        float slo = 0.f;
        float shi = 0.f;
        unsigned pPk[8][2];
        #pragma unroll
        for (int j = 0; j < 8; ++j) {
            float e0 = fmaf(sAcc[j][0], L2E, -mlo2);
            float e1 = fmaf(sAcc[j][1], L2E, -mlo2);
            float e2 = fmaf(sAcc[j][2], L2E, -mhi2);
            float e3 = fmaf(sAcc[j][3], L2E, -mhi2);
            unsigned plo = ex2h2(packh2(e0, e1));
            unsigned phi = ex2h2(packh2(e2, e3));
            pPk[j][0] = plo;
            pPk[j][1] = phi;
            float2 flo = __half22float2(*(__half2*)&plo);
            float2 fhi = __half22float2(*(__half2*)&phi);
            slo += flo.x + flo.y;
            shi += fhi.x + fhi.y;
        }
        // Skip the O rescale when NO lane's max moved (exact: expf(0)==1).
        bool noup = (sclo == 1.0f) && (schi == 1.0f);
        if (__all_sync(0xffffffffu, noup)) {
            l_lo += slo;
            l_hi += shi;
        } else {
            l_lo = l_lo * sclo + slo;
            l_hi = l_hi * schi + shi;
            #pragma unroll
            for (int n = 0; n < 4; ++n) {
                oAcc[n][0] *= sclo;
                oAcc[n][1] *= sclo;
                oAcc[n][2] *= schi;
                oAcc[n][3] *= schi;
            }
        }

        // oAcc += P V
        #pragma unroll
        for (int s = 0; s < 4; ++s) {
            unsigned aP[4];
            aP[0] = pPk[2*s][0];
            aP[1] = pPk[2*s][1];
            aP[2] = pPk[2*s+1][0];
            aP[3] = pPk[2*s+1][1];
            #pragma unroll
            for (int pr = 0; pr < 2; ++pr) {
                unsigned bvf[4];
                unsigned rv = vsB + (((pr * 16 + brow) * VSTR + s * 16 + bcol) << 1);
                ldmx4(bvf[0], bvf[1], bvf[2], bvf[3], rv);
                mma16816(oAcc[2*pr],   aP, &bvf[0], oAcc[2*pr]);
                mma16816(oAcc[2*pr+1], aP, &bvf[2], oAcc[2*pr+1]);
            }
        }

        if (kc < 15) {
            CP_WAIT0();
            __syncthreads();
        }
    }

    // quad-reduce the lane-local l partials (once)
    l_lo += __shfl_xor_sync(0xffffffffu, l_lo, 1);
    l_lo += __shfl_xor_sync(0xffffffffu, l_lo, 2);
    l_hi += __shfl_xor_sync(0xffffffffu, l_hi, 1);
    l_hi += __shfl_xor_sync(0xffffffffu, l_hi, 2);

    // normalize, stage Y as half into Ysm (= Qsm alias; per-warp rows)
    {
        float ilo = 1.0f / l_lo;
        float ihi = 1.0f / l_hi;
        int rlo = warp * 16 + (lane >> 2);
        int cb  = (lane & 3) * 2;
        #pragma unroll
        for (int n = 0; n < 4; ++n) {
            int c = n * 8 + cb;
            *(__half2*)&Ysm[rlo * QSTR + c] =
                __floats2half2_rn(oAcc[n][0] * ilo, oAcc[n][1] * ilo);
            *(__half2*)&Ysm[(rlo + 8) * QSTR + c] =
                __floats2half2_rn(oAcc[n][2] * ihi, oAcc[n][3] * ihi);
        }
    }
    __syncthreads();   // Ysm complete; Ksm/Vsm dead -> osm may overwrite

    // ---- fused output conv: out = Y * w_W^T + b_W + x ----
    unsigned aY0[4];
    unsigned aY1[4];
    {
        int arow = lane & 15;
        int acol = (lane >> 4) << 3;
        unsigned base = smem_u32(Ysm);
        unsigned ad = base + (((warp * 16 + arow) * QSTR + acol) << 1);
        ldmx4(aY0[0], aY0[1], aY0[2], aY0[3], ad);
        ldmx4(aY1[0], aY1[1], aY1[2], aY1[3], ad + 32);
    }

    const unsigned wBase = smem_u32(wsm);
    float cf[8][4];
    #pragma unroll
    for (int nt = 0; nt < 8; ++nt) {
        cf[nt][0] = 0.f; cf[nt][1] = 0.f; cf[nt][2] = 0.f; cf[nt][3] = 0.f;
    }
    #pragma unroll
    for (int g = 0; g < 4; ++g) {
        unsigned bw[4];
        unsigned ra = wBase + (((g * 16 + brow) * QSTR + bcol) << 1);
        ldmx4(bw[0], bw[1], bw[2], bw[3], ra);
        mma16816(cf[2*g],   aY0, &bw[0], cf[2*g]);
        mma16816(cf[2*g+1], aY0, &bw[2], cf[2*g+1]);
        ldmx4(bw[0], bw[1], bw[2], bw[3], ra + 32);
        mma16816(cf[2*g],   aY1, &bw[0], cf[2*g]);
        mma16816(cf[2*g+1], aY1, &bw[2], cf[2*g+1]);
    }

    // stage to osm[out][px] with bias
    {
        int rlo = warp * 16 + (lane >> 2);
        int cb  = (lane & 3) * 2;
        #pragma unroll
        for (int nt = 0; nt < 8; ++nt) {
            int c = nt * 8 + cb;
            float bc0 = bsd[c];
            float bc1 = bsd[c + 1];
            osm[c * OSTR + rlo]           = cf[nt][0] + bc0;
            osm[(c + 1) * OSTR + rlo]     = cf[nt][1] + bc1;
            osm[c * OSTR + rlo + 8]       = cf[nt][2] + bc0;
            osm[(c + 1) * OSTR + rlo + 8] = cf[nt][3] + bc1;
        }
    }
    __syncthreads();

    // residual add + store: 128 px x 64 out = 2048 float4
    {
        #pragma unroll
        for (int i = 0; i < 8; ++i) {
            int idx = t + i * 256;
            int co = idx >> 5;
            int p4 = idx & 31;
            float4 yv = *(const float4*)&osm[co * OSTR + p4 * 4];
            size_t gi = ((size_t)b * CI + co) * HW + q0 + p4 * 4;
            float4 xv = *(const float4*)&xg[gi];
            float4 ov;
            ov.x = yv.x + xv.x;
            ov.y = yv.y + xv.y;
            ov.z = yv.z + xv.z;
            ov.w = yv.w + xv.w;
            *(float4*)&outg[gi] = ov;
        }
    }
}

// ---------------------------------------------------------------------------
extern "C" void kernel_launch(void* const* d_in, const int* in_sizes, int n_in,
                              void* d_out, int out_size)
{
    const float* xg   = (const float*)d_in[0];
    const float* w_or = (const float*)d_in[1];
    const float* b_or = (const float*)d_in[2];
    const float* w_th = (const float*)d_in[3];
    const float* b_th = (const float*)d_in[4];
    const float* w_ph = (const float*)d_in[5];
    const float* b_ph = (const float*)d_in[6];
    const float* w_W  = (const float*)d_in[7];
    const float* b_W  = (const float*)d_in[8];
    float* outg = (float*)d_out;

    cudaFuncSetAttribute(qkv_kernel, cudaFuncAttributeMaxDynamicSharedMemorySize,
                         SMEM1_BYTES);
    cudaFuncSetAttribute(attn_kernel, cudaFuncAttributeMaxDynamicSharedMemorySize,
                         SMEM2_BYTES);

    qkv_kernel<<<dim3(32, NB), 256, SMEM1_BYTES>>>(xg, w_or, b_or, w_th, b_th,
                                                   w_ph, b_ph);
    attn_kernel<<<dim3(32, NB), 256, SMEM2_BYTES>>>(xg, w_W, b_W, outg);
}

// round 10
// speedup vs baseline: 12.1635x; 1.0061x over previous
#include <cuda_runtime.h>
#include <cuda_fp16.h>

#define NB   16
#define CI   64
#define CM   32
#define HW   4096
#define NKV  1024

// Scratch (static device globals; no allocation allowed)
__device__ __half Qh[(size_t)NB * HW * CM];    // [B][4096 q][32 c]
__device__ __half Kh[(size_t)NB * NKV * CM];   // [B][1024 kv][32 c]
__device__ __half Vth[(size_t)NB * CM * NKV];  // [B][32 c][1024 kv]

// ---------------------------------------------------------------------------
// helpers
// ---------------------------------------------------------------------------
__device__ __forceinline__ unsigned smem_u32(const void* p) {
    return (unsigned)__cvta_generic_to_shared(p);
}

__device__ __forceinline__ void ldmx4(unsigned& r0, unsigned& r1, unsigned& r2,
                                      unsigned& r3, unsigned addr) {
    asm volatile("ldmatrix.sync.aligned.m8n8.x4.shared.b16 {%0,%1,%2,%3}, [%4];\n"
                 : "=r"(r0), "=r"(r1), "=r"(r2), "=r"(r3) : "r"(addr));
}

__device__ __forceinline__ void mma16816(float* dd, const unsigned* aa,
                                         const unsigned* bb, const float* cc) {
    asm volatile(
        "mma.sync.aligned.m16n8k16.row.col.f32.f16.f16.f32 "
        "{%0,%1,%2,%3},{%4,%5,%6,%7},{%8,%9},{%10,%11,%12,%13};\n"
        : "=f"(dd[0]), "=f"(dd[1]), "=f"(dd[2]), "=f"(dd[3])
        : "r"(aa[0]), "r"(aa[1]), "r"(aa[2]), "r"(aa[3]),
          "r"(bb[0]), "r"(bb[1]),
          "f"(cc[0]), "f"(cc[1]), "f"(cc[2]), "f"(cc[3]));
}

__device__ __forceinline__ unsigned packh2(float av, float bv) {
    __half2 hh = __floats2half2_rn(av, bv);
    return *(unsigned*)&hh;
}

__device__ __forceinline__ unsigned ex2h2(unsigned in) {
    unsigned r;
    asm("ex2.approx.f16x2 %0, %1;\n" : "=r"(r) : "r"(in));
    return r;
}

#define CP_ASYNC16(sa, g) \
    asm volatile("cp.async.cg.shared.global [%0], [%1], 16;\n" :: "r"(sa), "l"(g))
#define CP_COMMIT() asm volatile("cp.async.commit_group;\n")
#define CP_WAIT0()  asm volatile("cp.async.wait_group 0;\n" ::: "memory")

#define L2E 1.4426950408889634f
#define ONES_H2 0x3C003C00u   // fp16 {1.0, 1.0}

// ---------------------------------------------------------------------------
// Kernel 1: qkv via tensor cores. 256 threads = 8 warps (16-px strip each).
// grid (32 row-pairs, B).
// ---------------------------------------------------------------------------
#define XSTR 72
#define WSTR 72
#define QKV_XSH   0
#define QKV_WSH   18432
#define QKV_BIAS  32256
#define SMEM1_BYTES (32256 + 384)

__global__ void __launch_bounds__(256, 3) qkv_kernel(
    const float* __restrict__ xg,
    const float* __restrict__ w_or, const float* __restrict__ b_or,
    const float* __restrict__ w_th, const float* __restrict__ b_th,
    const float* __restrict__ w_ph, const float* __restrict__ b_ph)
{
    extern __shared__ char smraw[];
    __half* xsh  = (__half*)(smraw + QKV_XSH);    // [128 px][XSTR]
    __half* wsh  = (__half*)(smraw + QKV_WSH);    // [96 out][WSTR]
    float*  bias = (float*)(smraw + QKV_BIAS);    // [96]
    float*  stg  = (float*)(smraw + QKV_XSH);     // alias: [128 px][33] fp32

    const int t    = threadIdx.x;
    const int warp = t >> 5;
    const int lane = t & 31;
    const int hp   = blockIdx.x;
    const int b    = blockIdx.y;

    // weights -> wsh (half): rows 0-31 theta, 32-63 phi, 64-95 origin
    for (int i = t; i < 2048; i += 256) {
        int r = i >> 6;
        int c = i & 63;
        wsh[r * WSTR + c]        = __float2half(w_th[i]);
        wsh[(32 + r) * WSTR + c] = __float2half(w_ph[i]);
        wsh[(64 + r) * WSTR + c] = __float2half(w_or[i]);
    }
    if (t < 32) {
        bias[t]      = b_th[t];
        bias[32 + t] = b_ph[t];
        bias[64 + t] = b_or[t];
    }

    // x tile: each thread loads 4 px x 8 ch as float4, packs, STS uint4
    {
        const int p0 = (t & 31) * 4;
        const int c0 = (t >> 5) * 8;
        const float* xb = xg + ((size_t)b * CI + c0) * HW + hp * 128 + p0;
        unsigned wbuf[4][4];
        #pragma unroll
        for (int cc = 0; cc < 4; ++cc) {
            float4 va = *(const float4*)(xb + (size_t)(2 * cc) * HW);
            float4 vb = *(const float4*)(xb + (size_t)(2 * cc + 1) * HW);
            wbuf[0][cc] = packh2(va.x, vb.x);
            wbuf[1][cc] = packh2(va.y, vb.y);
            wbuf[2][cc] = packh2(va.z, vb.z);
            wbuf[3][cc] = packh2(va.w, vb.w);
        }
        #pragma unroll
        for (int j = 0; j < 4; ++j) {
            uint4 u0;
            u0.x = wbuf[j][0]; u0.y = wbuf[j][1]; u0.z = wbuf[j][2]; u0.w = wbuf[j][3];
            *(uint4*)&xsh[(p0 + j) * XSTR + c0] = u0;
        }
    }
    __syncthreads();

    // A fragments: warp px strip [warp*16, warp*16+15], 4 k-steps
    unsigned aX[4][4];
    {
        int arow = lane & 15;
        int acol = (lane >> 4) << 3;
        unsigned base = smem_u32(xsh);
        #pragma unroll
        for (int k = 0; k < 4; ++k) {
            unsigned ad = base +
                (((warp * 16 + arow) * XSTR + k * 16 + acol) << 1);
            ldmx4(aX[k][0], aX[k][1], aX[k][2], aX[k][3], ad);
        }
    }
    __syncthreads();   // xsh is now dead; stg may overwrite it

    const int brow = ((lane >> 4) << 3) + (lane & 7);
    const int bcol = ((lane >> 3) & 1) << 3;
    const unsigned wshBase = smem_u32(wsh);

    #pragma unroll 1
    for (int g = 0; g < 3; ++g) {
        float cf[4][4];
        #pragma unroll
        for (int nt = 0; nt < 4; ++nt) {
            cf[nt][0] = 0.f; cf[nt][1] = 0.f; cf[nt][2] = 0.f; cf[nt][3] = 0.f;
        }
        #pragma unroll
        for (int nt2 = 0; nt2 < 2; ++nt2) {
            #pragma unroll
            for (int k = 0; k < 4; ++k) {
                unsigned bw[4];
                unsigned ra = wshBase +
                    (((g * 32 + nt2 * 16 + brow) * WSTR + k * 16 + bcol) << 1);
                ldmx4(bw[0], bw[1], bw[2], bw[3], ra);
                mma16816(cf[nt2*2],   aX[k], &bw[0], cf[nt2*2]);
                mma16816(cf[nt2*2+1], aX[k], &bw[2], cf[nt2*2+1]);
            }
        }
        // add bias
        #pragma unroll
        for (int nt = 0; nt < 4; ++nt) {
            int o0 = g * 32 + nt * 8 + (lane & 3) * 2;
            cf[nt][0] += bias[o0];
            cf[nt][1] += bias[o0 + 1];
            cf[nt][2] += bias[o0];
            cf[nt][3] += bias[o0 + 1];
        }

        if (g == 0) {
            __half2* Qb = (__half2*)(Qh + ((size_t)b * HW + hp * 128) * CM);
            int row = warp * 16 + (lane >> 2);
            #pragma unroll
            for (int nt = 0; nt < 4; ++nt) {
                int cp = (nt * 8 + (lane & 3) * 2) >> 1;
                Qb[row * 16 + cp]       = __floats2half2_rn(cf[nt][0], cf[nt][1]);
                Qb[(row + 8) * 16 + cp] = __floats2half2_rn(cf[nt][2], cf[nt][3]);
            }
        } else {
            int row = warp * 16 + (lane >> 2);
            #pragma unroll
            for (int nt = 0; nt < 4; ++nt) {
                int c0 = nt * 8 + (lane & 3) * 2;
                stg[row * 33 + c0]           = cf[nt][0];
                stg[row * 33 + c0 + 1]       = cf[nt][1];
                stg[(row + 8) * 33 + c0]     = cf[nt][2];
                stg[(row + 8) * 33 + c0 + 1] = cf[nt][3];
            }
            __syncthreads();
            if (g == 1) {
                #pragma unroll
                for (int i = 0; i < 4; ++i) {
                    int idx = t + i * 256;
                    int kw = idx >> 5;
                    int o  = idx & 31;
                    float mv = fmaxf(
                        fmaxf(stg[(2*kw) * 33 + o], stg[(2*kw + 1) * 33 + o]),
                        fmaxf(stg[(64 + 2*kw) * 33 + o], stg[(65 + 2*kw) * 33 + o]));
                    Kh[((size_t)b * NKV + hp * 32 + kw) * CM + o] = __float2half(mv);
                }
            } else {
                #pragma unroll
                for (int i = 0; i < 4; ++i) {
                    int idx = t + i * 256;
                    int o  = idx >> 5;
                    int kw = idx & 31;
                    float mv = fmaxf(
                        fmaxf(stg[(2*kw) * 33 + o], stg[(2*kw + 1) * 33 + o]),
                        fmaxf(stg[(64 + 2*kw) * 33 + o], stg[(65 + 2*kw) * 33 + o]));
                    Vth[((size_t)b * CM + o) * NKV + hp * 32 + kw] = __float2half(mv);
                }
            }
            __syncthreads();
        }
    }
}

// ---------------------------------------------------------------------------
// Kernel 2: FUSED attention + output conv + residual.
// grid (32 q-tiles of 128, B), 256 threads = 8 warps.
// Softmax denominator computed via MMA with a ones B-fragment (no scalar
// conversions/adds in the mainloop).
// ---------------------------------------------------------------------------
#define QSTR 40
#define VSTR 72
#define OSTR 132
#define AT_QSM  0
#define AT_WSM  10240
#define AT_BSD  15360
#define AT_KSM  15616
#define AT_VSM  25856
#define AT_OSM  15616              // alias over Ksm+Vsm (dead after mainloop)
#define SMEM2_BYTES (15616 + 64 * OSTR * 4)   // 49408

__global__ void __launch_bounds__(256, 3) attn_kernel(
    const float* __restrict__ xg, const float* __restrict__ w_W,
    const float* __restrict__ b_W, float* __restrict__ outg)
{
    extern __shared__ char atraw[];
    __half* Qsm = (__half*)(atraw + AT_QSM);   // [128 q][QSTR]; Ysm in epilogue
    __half* wsm = (__half*)(atraw + AT_WSM);   // [64 out][QSTR]
    float*  bsd = (float*)(atraw + AT_BSD);    // [64]
    __half* Ksm = (__half*)(atraw + AT_KSM);   // 2 x [64 kv][QSTR]
    __half* Vsm = (__half*)(atraw + AT_VSM);   // 2 x [32 c][VSTR]
    float*  osm = (float*)(atraw + AT_OSM);    // [64 out][OSTR] (alias)
    __half* Ysm = Qsm;

    const int t    = threadIdx.x;
    const int warp = t >> 5;
    const int lane = t & 31;
    const int b    = blockIdx.y;
    const int q0   = blockIdx.x * 128;

    // prologue: Q tile + chunk 0 of K/V via cp.async; w_W/b_W via plain loads
    {
        #pragma unroll
        for (int i = 0; i < 2; ++i) {
            int idx = t + i * 256;
            int row = idx >> 2;
            int seg = idx & 3;
            CP_ASYNC16(smem_u32(&Qsm[row * QSTR + seg * 8]),
                       Qh + ((size_t)b * HW + q0 + row) * CM + seg * 8);
        }
        {
            int row = t >> 2;
            int seg = t & 3;
            CP_ASYNC16(smem_u32(&Ksm[row * QSTR + seg * 8]),
                       Kh + ((size_t)b * NKV + row) * CM + seg * 8);
        }
        {
            int row = t >> 3;
            int seg = t & 7;
            CP_ASYNC16(smem_u32(&Vsm[row * VSTR + seg * 8]),
                       Vth + ((size_t)b * CM + row) * NKV + seg * 8);
        }
        for (int i = t; i < 2048; i += 256) {
            wsm[(i >> 5) * QSTR + (i & 31)] = __float2half(w_W[i]);
        }
        if (t < 64) {
            bsd[t] = b_W[t];
        }
        CP_COMMIT();
        CP_WAIT0();
        __syncthreads();
    }

    // A-operand (Q) fragments for 2 k-steps
    unsigned aQ0[4];
    unsigned aQ1[4];
    {
        int arow = lane & 15;
        int acol = (lane >> 4) << 3;
        unsigned base = smem_u32(Qsm);
        unsigned ad0 = base + (((warp * 16 + arow) * QSTR + acol) << 1);
        ldmx4(aQ0[0], aQ0[1], aQ0[2], aQ0[3], ad0);
        ldmx4(aQ1[0], aQ1[1], aQ1[2], aQ1[3], ad0 + 32);
    }

    const int brow = ((lane >> 4) << 3) + (lane & 7);
    const int bcol = ((lane >> 3) & 1) << 3;
    const unsigned ksBase = smem_u32(Ksm);
    const unsigned vsBase = smem_u32(Vsm);

    float oAcc[4][4];
    #pragma unroll
    for (int n = 0; n < 4; ++n) {
        oAcc[n][0] = 0.f; oAcc[n][1] = 0.f; oAcc[n][2] = 0.f; oAcc[n][3] = 0.f;
    }
    float lAcc[4];      // row-sum accumulator via ones-MMA: [0]=row lo, [2]=row hi
    lAcc[0] = 0.f; lAcc[1] = 0.f; lAcc[2] = 0.f; lAcc[3] = 0.f;
    const unsigned onesB[2] = { ONES_H2, ONES_H2 };

    float m_lo = -1e30f;
    float m_hi = -1e30f;

    for (int kc = 0; kc < 16; ++kc) {
        const int cur = kc & 1;
        if (kc < 15) {
            int nxt = cur ^ 1;
            {
                int row = t >> 2;
                int seg = t & 3;
                CP_ASYNC16(smem_u32(&Ksm[nxt * 64 * QSTR + row * QSTR + seg * 8]),
                           Kh + ((size_t)b * NKV + (kc + 1) * 64 + row) * CM + seg * 8);
            }
            {
                int row = t >> 3;
                int seg = t & 7;
                CP_ASYNC16(smem_u32(&Vsm[nxt * 32 * VSTR + row * VSTR + seg * 8]),
                           Vth + ((size_t)b * CM + row) * NKV + (kc + 1) * 64 + seg * 8);
            }
            CP_COMMIT();
        }
        const unsigned ksB = ksBase + cur * (64 * QSTR * 2);
        const unsigned vsB = vsBase + cur * (32 * VSTR * 2);

        // sAcc = Q K^T for this 64-kv chunk
        float sAcc[8][4];
        #pragma unroll
        for (int j = 0; j < 8; ++j) {
            sAcc[j][0] = 0.f; sAcc[j][1] = 0.f; sAcc[j][2] = 0.f; sAcc[j][3] = 0.f;
        }
        #pragma unroll
        for (int g = 0; g < 4; ++g) {
            unsigned bkf[4];
            unsigned ra = ksB + (((g * 16 + brow) * QSTR + bcol) << 1);
            ldmx4(bkf[0], bkf[1], bkf[2], bkf[3], ra);
            mma16816(sAcc[2*g],   aQ0, &bkf[0], sAcc[2*g]);
            mma16816(sAcc[2*g+1], aQ0, &bkf[2], sAcc[2*g+1]);
            ldmx4(bkf[0], bkf[1], bkf[2], bkf[3], ra + 32);
            mma16816(sAcc[2*g],   aQ1, &bkf[0], sAcc[2*g]);
            mma16816(sAcc[2*g+1], aQ1, &bkf[2], sAcc[2*g+1]);
        }

        // online softmax: packed half2 max reduce (2 shuffles)
        float mlo = -1e30f;
        float mhi = -1e30f;
        #pragma unroll
        for (int j = 0; j < 8; ++j) {
            mlo = fmaxf(mlo, fmaxf(sAcc[j][0], sAcc[j][1]));
            mhi = fmaxf(mhi, fmaxf(sAcc[j][2], sAcc[j][3]));
        }
        {
            unsigned mp = packh2(mlo, mhi);
            __half2 mh = *(__half2*)&mp;
            unsigned ms1 = __shfl_xor_sync(0xffffffffu, mp, 1);
            mh = __hmax2(mh, *(__half2*)&ms1);
            unsigned mhu = *(unsigned*)&mh;
            unsigned ms2 = __shfl_xor_sync(0xffffffffu, mhu, 2);
            mh = __hmax2(mh, *(__half2*)&ms2);
            mlo = __low2float(mh);
            mhi = __high2float(mh);
        }
        float nmlo = fmaxf(m_lo, mlo);
        float nmhi = fmaxf(m_hi, mhi);
        float sclo = __expf(m_lo - nmlo);
        float schi = __expf(m_hi - nmhi);
        m_lo = nmlo;
        m_hi = nmhi;

        // P = exp(s - m) in fp16x2 via ex2.approx.f16x2 (no scalar sums)
        const float mlo2 = nmlo * L2E;
        const float mhi2 = nmhi * L2E;
        unsigned pPk[8][2];
        #pragma unroll
        for (int j = 0; j < 8; ++j) {
            float e0 = fmaf(sAcc[j][0], L2E, -mlo2);
            float e1 = fmaf(sAcc[j][1], L2E, -mlo2);
            float e2 = fmaf(sAcc[j][2], L2E, -mhi2);
            float e3 = fmaf(sAcc[j][3], L2E, -mhi2);
            pPk[j][0] = ex2h2(packh2(e0, e1));
            pPk[j][1] = ex2h2(packh2(e2, e3));
        }

        // Skip the rescale when NO lane's max moved (exact: expf(0)==1).
        bool noup = (sclo == 1.0f) && (schi == 1.0f);
        if (!__all_sync(0xffffffffu, noup)) {
            #pragma unroll
            for (int n = 0; n < 4; ++n) {
                oAcc[n][0] *= sclo;
                oAcc[n][1] *= sclo;
                oAcc[n][2] *= schi;
                oAcc[n][3] *= schi;
            }
            lAcc[0] *= sclo;
            lAcc[1] *= sclo;
            lAcc[2] *= schi;
            lAcc[3] *= schi;
        }

        // oAcc += P V ; lAcc += P * ones (row-sum via tensor core)
        #pragma unroll
        for (int s = 0; s < 4; ++s) {
            unsigned aP[4];
            aP[0] = pPk[2*s][0];
            aP[1] = pPk[2*s][1];
            aP[2] = pPk[2*s+1][0];
            aP[3] = pPk[2*s+1][1];
            #pragma unroll
            for (int pr = 0; pr < 2; ++pr) {
                unsigned bvf[4];
                unsigned rv = vsB + (((pr * 16 + brow) * VSTR + s * 16 + bcol) << 1);
                ldmx4(bvf[0], bvf[1], bvf[2], bvf[3], rv);
                mma16816(oAcc[2*pr],   aP, &bvf[0], oAcc[2*pr]);
                mma16816(oAcc[2*pr+1], aP, &bvf[2], oAcc[2*pr+1]);
            }
            mma16816(lAcc, aP, onesB, lAcc);
        }

        if (kc < 15) {
            CP_WAIT0();
            __syncthreads();
        }
    }

    // l from the ones-MMA accumulator (k-reduction already complete)
    float l_lo = lAcc[0];
    float l_hi = lAcc[2];

    // normalize, stage Y as half into Ysm (= Qsm alias; per-warp rows)
    {
        float ilo = 1.0f / l_lo;
        float ihi = 1.0f / l_hi;
        int rlo = warp * 16 + (lane >> 2);
        int cb  = (lane & 3) * 2;
        #pragma unroll
        for (int n = 0; n < 4; ++n) {
            int c = n * 8 + cb;
            *(__half2*)&Ysm[rlo * QSTR + c] =
                __floats2half2_rn(oAcc[n][0] * ilo, oAcc[n][1] * ilo);
            *(__half2*)&Ysm[(rlo + 8) * QSTR + c] =
                __floats2half2_rn(oAcc[n][2] * ihi, oAcc[n][3] * ihi);
        }
    }
    __syncthreads();   // Ysm complete; Ksm/Vsm dead -> osm may overwrite

    // ---- fused output conv: out = Y * w_W^T + b_W + x ----
    unsigned aY0[4];
    unsigned aY1[4];
    {
        int arow = lane & 15;
        int acol = (lane >> 4) << 3;
        unsigned base = smem_u32(Ysm);
        unsigned ad = base + (((warp * 16 + arow) * QSTR + acol) << 1);
        ldmx4(aY0[0], aY0[1], aY0[2], aY0[3], ad);
        ldmx4(aY1[0], aY1[1], aY1[2], aY1[3], ad + 32);
    }

    const unsigned wBase = smem_u32(wsm);
    float cf[8][4];
    #pragma unroll
    for (int nt = 0; nt < 8; ++nt) {
        cf[nt][0] = 0.f; cf[nt][1] = 0.f; cf[nt][2] = 0.f; cf[nt][3] = 0.f;
    }
    #pragma unroll
    for (int g = 0; g < 4; ++g) {
        unsigned bw[4];
        unsigned ra = wBase + (((g * 16 + brow) * QSTR + bcol) << 1);
        ldmx4(bw[0], bw[1], bw[2], bw[3], ra);
        mma16816(cf[2*g],   aY0, &bw[0], cf[2*g]);
        mma16816(cf[2*g+1], aY0, &bw[2], cf[2*g+1]);
        ldmx4(bw[0], bw[1], bw[2], bw[3], ra + 32);
        mma16816(cf[2*g],   aY1, &bw[0], cf[2*g]);
        mma16816(cf[2*g+1], aY1, &bw[2], cf[2*g+1]);
    }

    // stage to osm[out][px] with bias
    {
        int rlo = warp * 16 + (lane >> 2);
        int cb  = (lane & 3) * 2;
        #pragma unroll
        for (int nt = 0; nt < 8; ++nt) {
            int c = nt * 8 + cb;
            float bc0 = bsd[c];
            float bc1 = bsd[c + 1];
            osm[c * OSTR + rlo]           = cf[nt][0] + bc0;
            osm[(c + 1) * OSTR + rlo]     = cf[nt][1] + bc1;
            osm[c * OSTR + rlo + 8]       = cf[nt][2] + bc0;
            osm[(c + 1) * OSTR + rlo + 8] = cf[nt][3] + bc1;
        }
    }
    __syncthreads();

    // residual add + store: 128 px x 64 out = 2048 float4
    {
        #pragma unroll
        for (int i = 0; i < 8; ++i) {
            int idx = t + i * 256;
            int co = idx >> 5;
            int p4 = idx & 31;
            float4 yv = *(const float4*)&osm[co * OSTR + p4 * 4];
            size_t gi = ((size_t)b * CI + co) * HW + q0 + p4 * 4;
            float4 xv = *(const float4*)&xg[gi];
            float4 ov;
            ov.x = yv.x + xv.x;
            ov.y = yv.y + xv.y;
            ov.z = yv.z + xv.z;
            ov.w = yv.w + xv.w;
            *(float4*)&outg[gi] = ov;
        }
    }
}

// ---------------------------------------------------------------------------
extern "C" void kernel_launch(void* const* d_in, const int* in_sizes, int n_in,
                              void* d_out, int out_size)
{
    const float* xg   = (const float*)d_in[0];
    const float* w_or = (const float*)d_in[1];
    const float* b_or = (const float*)d_in[2];
    const float* w_th = (const float*)d_in[3];
    const float* b_th = (const float*)d_in[4];
    const float* w_ph = (const float*)d_in[5];
    const float* b_ph = (const float*)d_in[6];
    const float* w_W  = (const float*)d_in[7];
    const float* b_W  = (const float*)d_in[8];
    float* outg = (float*)d_out;

    cudaFuncSetAttribute(qkv_kernel, cudaFuncAttributeMaxDynamicSharedMemorySize,
                         SMEM1_BYTES);
    cudaFuncSetAttribute(attn_kernel, cudaFuncAttributeMaxDynamicSharedMemorySize,
                         SMEM2_BYTES);

    qkv_kernel<<<dim3(32, NB), 256, SMEM1_BYTES>>>(xg, w_or, b_or, w_th, b_th,
                                                   w_ph, b_ph);
    attn_kernel<<<dim3(32, NB), 256, SMEM2_BYTES>>>(xg, w_W, b_W, outg);
}